// round 14
// baseline (speedup 1.0000x reference)
#include <cuda_runtime.h>
#include <cuda_bf16.h>
#include <math.h>
#include <stdint.h>

#define Nn 20000
#define Dd 256
#define Ss 4
#define Ee 320000
#define Hh 5
#define SN (Ss * Nn)
#define NB 79                      // ceil(Nn/256)

// ---------------- scratch (device globals; no allocs allowed) ----------------
__device__ float g_deg[Nn];
__device__ float g_dinv[Nn];
__device__ int   g_cnt[Nn];
__device__ int   g_rowp[Nn + 1];
__device__ int   g_fill[Nn];
__device__ int   g_bsum[NB + 1];
__device__ int   g_boff[NB + 1];
__device__ int   g_csrc[Ee];
__device__ float g_cnorm[Ee];

__device__ float g_tmpW[SN * Dd];
__device__ float g_giAll[SN * 3 * Dd];
__device__ float g_gh[Nn * 3 * Dd];
__device__ float g_h1[Nn * Dd];
__device__ float g_h2[Nn * Dd];
__device__ float g_f2[Nn * 64];
__device__ float g_d1[Nn * 64];
__device__ float g_cb[192];

// split-bf16 activations: layout [rows, 2K] = [hi | lo]
__device__ __nv_bfloat16 g_xs[SN * 512];
__device__ __nv_bfloat16 g_aggA[SN * 512];
__device__ __nv_bfloat16 g_seqs[SN * 512];
__device__ __nv_bfloat16 g_hs[Nn * 512];
__device__ __nv_bfloat16 g_f1s[Nn * 256];

// split-bf16 weights: [M, 2K]
__device__ __nv_bfloat16 g_gcnWs[3 * 256 * 512];
__device__ __nv_bfloat16 g_Wihs[768 * 512];
__device__ __nv_bfloat16 g_Whhs[768 * 512];
__device__ __nv_bfloat16 g_cWs[192 * 512];
__device__ __nv_bfloat16 g_fc2Ws[64 * 256];

// ---------------- helpers ----------------
__device__ __forceinline__ void split_write(float v, __nv_bfloat16* hi, __nv_bfloat16* lo) {
    __nv_bfloat16 h = __float2bfloat16(v);
    *hi = h;
    *lo = __float2bfloat16(v - __bfloat162float(h));
}
__device__ __forceinline__ void split_write2(float v0, float v1,
                                             __nv_bfloat16* hi, __nv_bfloat16* lo) {
    __nv_bfloat16 h0 = __float2bfloat16(v0), h1 = __float2bfloat16(v1);
    __nv_bfloat162 hh; hh.x = h0; hh.y = h1;
    *reinterpret_cast<__nv_bfloat162*>(hi) = hh;
    __nv_bfloat162 ll;
    ll.x = __float2bfloat16(v0 - __bfloat162float(h0));
    ll.y = __float2bfloat16(v1 - __bfloat162float(h1));
    *reinterpret_cast<__nv_bfloat162*>(lo) = ll;
}
__device__ __forceinline__ void split_write4(float4 v, __nv_bfloat16* hi, __nv_bfloat16* lo) {
    split_write2(v.x, v.y, hi, lo);
    split_write2(v.z, v.w, hi + 2, lo + 2);
}
__device__ __forceinline__ void ldsm4(uint32_t* r, uint32_t addr) {
    asm volatile("ldmatrix.sync.aligned.m8n8.x4.shared.b16 {%0,%1,%2,%3}, [%4];"
                 : "=r"(r[0]), "=r"(r[1]), "=r"(r[2]), "=r"(r[3]) : "r"(addr));
}
__device__ __forceinline__ void mma16816(float* c, const uint32_t* a, const uint32_t* b) {
    asm volatile(
        "mma.sync.aligned.m16n8k16.row.col.f32.bf16.bf16.f32 "
        "{%0,%1,%2,%3}, {%4,%5,%6,%7}, {%8,%9}, {%0,%1,%2,%3};"
        : "+f"(c[0]), "+f"(c[1]), "+f"(c[2]), "+f"(c[3])
        : "r"(a[0]), "r"(a[1]), "r"(a[2]), "r"(a[3]), "r"(b[0]), "r"(b[1]));
}
__device__ __forceinline__ void cpa16z(uint32_t dst, const void* src, int sz) {
    asm volatile("cp.async.cg.shared.global [%0], [%1], 16, %2;"
                 :: "r"(dst), "l"(src), "r"(sz));
}
__device__ __forceinline__ float gelu1(float v) {
    return 0.5f * v * (1.0f + erff(v * 0.7071067811865475f));
}

// ---------------- graph preprocessing ----------------
__global__ void k_init_deg_cnt() {
    int i = blockIdx.x * blockDim.x + threadIdx.x;
    if (i < Nn) { g_deg[i] = 1.0f; g_cnt[i] = 0; }
}
__global__ void k_edge_deg_cnt(const int* __restrict__ dst, const float* __restrict__ w) {
    int e = blockIdx.x * blockDim.x + threadIdx.x;
    if (e < Ee) {
        int t = dst[e];
        atomicAdd(&g_deg[t], w[e]);
        atomicAdd(&g_cnt[t], 1);
    }
}
__global__ void k_dinv() {
    int i = blockIdx.x * blockDim.x + threadIdx.x;
    if (i < Nn) g_dinv[i] = rsqrtf(g_deg[i]);
}
__global__ void __launch_bounds__(256) k_scan1() {
    __shared__ int wsum[8];
    int i = blockIdx.x * 256 + threadIdx.x;
    int lane = threadIdx.x & 31, wd = threadIdx.x >> 5;
    int v = (i < Nn) ? g_cnt[i] : 0;
    int x = v;
#pragma unroll
    for (int o = 1; o < 32; o <<= 1) {
        int y = __shfl_up_sync(0xffffffffu, x, o);
        if (lane >= o) x += y;
    }
    if (lane == 31) wsum[wd] = x;
    __syncthreads();
    if (threadIdx.x == 0) {
        int acc = 0;
#pragma unroll
        for (int w = 0; w < 8; w++) { int t = wsum[w]; wsum[w] = acc; acc += t; }
        g_bsum[blockIdx.x] = acc;
    }
    __syncthreads();
    if (i < Nn) g_rowp[i] = wsum[wd] + x - v;
}
__global__ void k_scan2() {
    int t = threadIdx.x;
    __shared__ int sh[NB];
    if (t < NB) sh[t] = g_bsum[t];
    __syncthreads();
    if (t == 0) {
        int acc = 0;
        for (int b = 0; b < NB; b++) { int v = sh[b]; g_boff[b] = acc; acc += v; }
        g_rowp[Nn] = acc;
    }
}
__global__ void __launch_bounds__(256) k_scan3() {
    int i = blockIdx.x * 256 + threadIdx.x;
    if (i < Nn) {
        int r = g_rowp[i] + g_boff[blockIdx.x];
        g_rowp[i] = r;
        g_fill[i] = r;
    }
}
__global__ void k_fill_csr(const int* __restrict__ src, const int* __restrict__ dst,
                           const float* __restrict__ w) {
    int e = blockIdx.x * blockDim.x + threadIdx.x;
    if (e < Ee) {
        int s = src[e], t = dst[e];
        int pos = atomicAdd(&g_fill[t], 1);
        g_csrc[pos]  = s;
        g_cnorm[pos] = g_dinv[s] * w[e] * g_dinv[t];
    }
}

// ---------------- split conversion kernels ----------------
__global__ void k_split(const float* __restrict__ in, __nv_bfloat16* __restrict__ out,
                        long total4, int K4) {
    long idx = (long)blockIdx.x * blockDim.x + threadIdx.x;
    if (idx >= total4) return;
    long r = idx / K4;
    int  c = (int)(idx - r * K4) * 4;
    int  K = K4 * 4;
    float4 v = *reinterpret_cast<const float4*>(in + r * K + c);
    split_write4(v, &out[r * 2 * K + c], &out[r * 2 * K + K + c]);
}
__global__ void k_splitT(const float* __restrict__ in, __nv_bfloat16* __restrict__ out,
                         int Kd, int Md) {
    long idx = (long)blockIdx.x * blockDim.x + threadIdx.x;
    if (idx >= (long)Kd * Md) return;
    int k = (int)(idx / Md);
    int m = (int)(idx - (long)k * Md);
    float v = in[idx];
    split_write(v, &out[(long)m * 2 * Kd + k], &out[(long)m * 2 * Kd + Kd + k]);
}

// ---------------- bf16 mma.sync GEMM, 256x128 tile, 512 thr, 1 CTA/SM ----------------
// C[R,M] = A[R,K] @ B[M,K]^T; A/B split: [rows, 2K] = [hi | lo].
// 16 warps as 4M x 4N, warp tile 64x32. 25% fewer cp.async ops vs 128x128 pair.
// MODE 0: fp32 outF. MODE 3: fused fc1|dh1 epilogue.
#define SROW2 40
#define A_ARR (256 * SROW2 * 2)            // 20480 B per A array
#define B_ARR (128 * SROW2 * 2)            // 10240 B per B array
#define STAGE_B (2 * A_ARR + 2 * B_ARR)    // 61440
#define GEMM_SMEM (2 * STAGE_B)            // 122880
template <int ACT, int MODE>
__global__ void __launch_bounds__(512, 1)
gemm_mma(const __nv_bfloat16* __restrict__ A, const __nv_bfloat16* __restrict__ B,
         const float* __restrict__ bias, float* __restrict__ outF,
         __nv_bfloat16* __restrict__ outS, int R, int M, int K) {
    extern __shared__ __align__(16) __nv_bfloat16 smg[];
    const uint32_t sbase = (uint32_t)__cvta_generic_to_shared(smg);

    const int tid  = threadIdx.x;
    const int lane = tid & 31, wid = tid >> 5;
    const int wm = wid & 3;                // M quarter (rows, 4 x 64)
    const int wn = wid >> 2;               // N quarter (cols, 4 x 32)
    const long rowA = (long)blockIdx.y * 256;
    const long colB = (long)blockIdx.x * 128;
    const int K2 = 2 * K;
    const int NC = K >> 5;

    // ---- hoisted loader: warp-uniform arrid = tid>>7 (0=Ah 1=Al 2=Bh 3=Bl) ----
    const int arrid = tid >> 7;
    const int l7    = tid & 127;
    const bool isA  = arrid < 2;
    const int nops  = isA ? 8 : 4;
    const int row0  = (l7 >> 2) * (isA ? 8 : 4);
    const int seg   = l7 & 3;
    const long rb   = (isA ? rowA : colB) + row0;
    const int  lim  = isA ? R : M;
    int szs[8];
#pragma unroll
    for (int u = 0; u < 8; u++) szs[u] = (u < nops && rb + u < lim) ? 16 : 0;
    const __nv_bfloat16* sp = (isA ? A : B) + rb * (long)K2 +
                              ((arrid & 1) ? K : 0) + seg * 8;
    const uint32_t arrbase = (arrid == 0) ? 0u
                           : (arrid == 1) ? (uint32_t)A_ARR
                           : (arrid == 2) ? (uint32_t)(2 * A_ARR)
                                          : (uint32_t)(2 * A_ARR + B_ARR);
    const uint32_t dstb = arrbase + (uint32_t)(row0 * SROW2 + seg * 8) * 2;

    float acc[4][4][4];
#pragma unroll
    for (int i = 0; i < 4; i++)
#pragma unroll
        for (int j = 0; j < 4; j++)
#pragma unroll
            for (int k = 0; k < 4; k++) acc[i][j][k] = 0.0f;

    auto ld_chunk = [&](int c, int buf) {
        uint32_t stg = sbase + (uint32_t)buf * STAGE_B + dstb;
        const __nv_bfloat16* s = sp + (long)c * 32;
#pragma unroll
        for (int u = 0; u < 8; u++)
            if (u < nops) cpa16z(stg + (uint32_t)(u * SROW2 * 2), s + (long)u * K2, szs[u]);
        asm volatile("cp.async.commit_group;" ::: "memory");
    };

    ld_chunk(0, 0);

    const uint32_t aOffC = ((uint32_t)(wm * 64 + (lane & 15)) * SROW2 + (lane >> 4) * 8) * 2;
    const uint32_t bOffC = ((uint32_t)(wn * 32 + ((lane >> 4) & 1) * 8 + (lane & 7)) * SROW2 +
                            ((lane >> 3) & 1) * 8) * 2;

    for (int c = 0; c < NC; c++) {
        int buf = c & 1;
        if (c + 1 < NC) {
            ld_chunk(c + 1, buf ^ 1);
            asm volatile("cp.async.wait_group 1;" ::: "memory");
        } else {
            asm volatile("cp.async.wait_group 0;" ::: "memory");
        }
        __syncthreads();
        uint32_t stg = sbase + (uint32_t)buf * STAGE_B;
        uint32_t ah = stg + aOffC;
        uint32_t al = ah + A_ARR;
        uint32_t bh = stg + 2 * A_ARR + bOffC;
        uint32_t bl = bh + B_ARR;
#pragma unroll
        for (int ks = 0; ks < 2; ks++) {
            uint32_t koff = (uint32_t)(ks * 16) * 2;
            uint32_t bhf[2][4], blf[2][4];
#pragma unroll
            for (int nt = 0; nt < 2; nt++) {
                ldsm4(bhf[nt], bh + (uint32_t)(nt * 16 * SROW2) * 2 + koff);
                ldsm4(blf[nt], bl + (uint32_t)(nt * 16 * SROW2) * 2 + koff);
            }
#pragma unroll
            for (int half = 0; half < 2; half++) {
                uint32_t ahf[2][4], alf[2][4];
#pragma unroll
                for (int m2 = 0; m2 < 2; m2++) {
                    int mt = half * 2 + m2;
                    ldsm4(ahf[m2], ah + (uint32_t)(mt * 16 * SROW2) * 2 + koff);
                    ldsm4(alf[m2], al + (uint32_t)(mt * 16 * SROW2) * 2 + koff);
                }
#pragma unroll
                for (int m2 = 0; m2 < 2; m2++)
#pragma unroll
                    for (int j = 0; j < 4; j++)
                        mma16816(acc[half * 2 + m2][j], ahf[m2], &bhf[j >> 1][(j & 1) * 2]);
#pragma unroll
                for (int m2 = 0; m2 < 2; m2++)
#pragma unroll
                    for (int j = 0; j < 4; j++)
                        mma16816(acc[half * 2 + m2][j], ahf[m2], &blf[j >> 1][(j & 1) * 2]);
#pragma unroll
                for (int m2 = 0; m2 < 2; m2++)
#pragma unroll
                    for (int j = 0; j < 4; j++)
                        mma16816(acc[half * 2 + m2][j], alf[m2], &bhf[j >> 1][(j & 1) * 2]);
            }
        }
        __syncthreads();
    }

    // vectorized epilogue
#pragma unroll
    for (int mt = 0; mt < 4; mt++) {
        long r0e = rowA + wm * 64 + mt * 16 + (lane >> 2);
#pragma unroll
        for (int j = 0; j < 4; j++) {
            int col0 = (int)colB + wn * 32 + j * 8 + (lane & 3) * 2;
            if (col0 >= M) continue;
            float2 b2 = make_float2(0.f, 0.f);
            if (bias) b2 = *reinterpret_cast<const float2*>(bias + col0);
#pragma unroll
            for (int half = 0; half < 2; half++) {
                long r = r0e + half * 8;
                if (r >= R) continue;
                float v0 = acc[mt][j][half * 2 + 0] + b2.x;
                float v1 = acc[mt][j][half * 2 + 1] + b2.y;
                if (ACT) { v0 = gelu1(v0); v1 = gelu1(v1); }
                if (MODE == 0) {
                    *reinterpret_cast<float2*>(outF + r * (long)M + col0) = make_float2(v0, v1);
                } else {   // MODE 3: fused fc1|dh1
                    if (col0 < 128)
                        split_write2(v0, v1, &outS[r * 256 + col0], &outS[r * 256 + 128 + col0]);
                    else
                        *reinterpret_cast<float2*>(outF + r * 64 + (col0 - 128)) =
                            make_float2(v0, v1);
                }
            }
        }
    }
}

// ---- GCN aggregate, 4 snapshots x 64-thread groups, float4 gathers ----
__global__ void __launch_bounds__(256)
k_gcn_agg4(const float* __restrict__ hW,
           const float* __restrict__ bias, const float* __restrict__ g,
           const float* __restrict__ b, __nv_bfloat16* __restrict__ out) {
    const int t  = blockIdx.x;
    const int si = threadIdx.x >> 6;       // snapshot group 0..3
    const int l6 = threadIdx.x & 63;
    const int d4 = l6 << 2;                // feature base (float4)
    const float di = g_dinv[t];
    const float di2 = di * di;
    const float* base = hW + (size_t)si * Nn * Dd;

    float4 acc = *reinterpret_cast<const float4*>(base + (size_t)t * Dd + d4);
    acc.x *= di2; acc.y *= di2; acc.z *= di2; acc.w *= di2;

    int e0 = g_rowp[t], e1 = g_rowp[t + 1];
#pragma unroll 2
    for (int e = e0; e < e1; e++) {
        int s = __ldg(&g_csrc[e]);
        float nm = __ldg(&g_cnorm[e]);
        float4 v = *reinterpret_cast<const float4*>(base + (size_t)s * Dd + d4);
        acc.x += nm * v.x; acc.y += nm * v.y; acc.z += nm * v.z; acc.w += nm * v.w;
    }
    float4 bb = *reinterpret_cast<const float4*>(bias + d4);
    acc.x += bb.x; acc.y += bb.y; acc.z += bb.z; acc.w += bb.w;

    // LN over this group's 256 values (64 threads x 4)
    __shared__ float rs[8], rq[8];
    __shared__ float mvm[Ss], mvr[Ss];
    float sum = acc.x + acc.y + acc.z + acc.w;
    float sq  = acc.x * acc.x + acc.y * acc.y + acc.z * acc.z + acc.w * acc.w;
    const int lane = threadIdx.x & 31, wd = threadIdx.x >> 5;
#pragma unroll
    for (int o = 16; o; o >>= 1) {
        sum += __shfl_down_sync(0xffffffffu, sum, o);
        sq  += __shfl_down_sync(0xffffffffu, sq, o);
    }
    if (lane == 0) { rs[wd] = sum; rq[wd] = sq; }
    __syncthreads();
    if (threadIdx.x < Ss) {
        float ss = rs[2 * threadIdx.x] + rs[2 * threadIdx.x + 1];
        float qq = rq[2 * threadIdx.x] + rq[2 * threadIdx.x + 1];
        float m = ss * (1.0f / 256.0f);
        float var = qq * (1.0f / 256.0f) - m * m;
        mvm[threadIdx.x] = m;
        mvr[threadIdx.x] = rsqrtf(var + 1e-5f);
    }
    __syncthreads();
    const float m = mvm[si], rstd = mvr[si];
    float4 gg = *reinterpret_cast<const float4*>(g + d4);
    float4 b2 = *reinterpret_cast<const float4*>(b + d4);
    float4 val;
    val.x = fmaxf((acc.x - m) * rstd * gg.x + b2.x, 0.0f);
    val.y = fmaxf((acc.y - m) * rstd * gg.y + b2.y, 0.0f);
    val.z = fmaxf((acc.z - m) * rstd * gg.z + b2.z, 0.0f);
    val.w = fmaxf((acc.w - m) * rstd * gg.w + b2.w, 0.0f);
    __nv_bfloat16* o = out + ((size_t)si * Nn + t) * 512;
    split_write4(val, &o[d4], &o[256 + d4]);
}

// ---------------- GRU cell, float4 vectorized ----------------
__global__ void k_gru_cell(const float* __restrict__ gi, const float* __restrict__ gh,
                           const float* __restrict__ bhh, const float* __restrict__ hprev,
                           float* __restrict__ hnew, __nv_bfloat16* __restrict__ hs,
                           int first) {
    int idx = blockIdx.x * blockDim.x + threadIdx.x;
    if (idx >= Nn * 64) return;
    int n = idx >> 6, d = (idx & 63) << 2;
    const float* gir = gi + (size_t)n * 768;
    float4 ir = *reinterpret_cast<const float4*>(gir + d);
    float4 iz = *reinterpret_cast<const float4*>(gir + 256 + d);
    float4 ig = *reinterpret_cast<const float4*>(gir + 512 + d);
    float4 hr, hz, hg, hp;
    if (first) {
        hr = *reinterpret_cast<const float4*>(bhh + d);
        hz = *reinterpret_cast<const float4*>(bhh + 256 + d);
        hg = *reinterpret_cast<const float4*>(bhh + 512 + d);
        hp = make_float4(0.f, 0.f, 0.f, 0.f);
    } else {
        const float* ghr = gh + (size_t)n * 768;
        hr = *reinterpret_cast<const float4*>(ghr + d);
        hz = *reinterpret_cast<const float4*>(ghr + 256 + d);
        hg = *reinterpret_cast<const float4*>(ghr + 512 + d);
        hp = *reinterpret_cast<const float4*>(hprev + (size_t)n * 256 + d);
    }
    float4 v;
#define GRU1(c) { \
        float r = 1.0f / (1.0f + expf(-(ir.c + hr.c))); \
        float z = 1.0f / (1.0f + expf(-(iz.c + hz.c))); \
        float ng = tanhf(ig.c + r * hg.c); \
        v.c = (1.0f - z) * ng + z * hp.c; }
    GRU1(x) GRU1(y) GRU1(z) GRU1(w)
#undef GRU1
    *reinterpret_cast<float4*>(hnew + (size_t)n * 256 + d) = v;
    split_write4(v, &hs[(size_t)n * 512 + d], &hs[(size_t)n * 512 + 256 + d]);
}

// ---------------- tiny head GEMM ----------------
__global__ void __launch_bounds__(256)
k_head5(const float* __restrict__ in, const float* __restrict__ W,
        const float* __restrict__ bias, float* __restrict__ out) {
    __shared__ float sW[5 * 64];
    for (int i = threadIdx.x; i < 5 * 64; i += blockDim.x) sW[i] = W[i];
    __syncthreads();
    int gw = (blockIdx.x * blockDim.x + threadIdx.x) >> 5;
    int lane = threadIdx.x & 31;
    if (gw >= Nn) return;
    float x0 = in[(size_t)gw * 64 + lane];
    float x1 = in[(size_t)gw * 64 + 32 + lane];
#pragma unroll
    for (int m = 0; m < 5; m++) {
        float p = x0 * sW[m * 64 + lane] + x1 * sW[m * 64 + 32 + lane];
#pragma unroll
        for (int o = 16; o; o >>= 1) p += __shfl_down_sync(0xffffffffu, p, o);
        if (lane == 0) out[(size_t)gw * 5 + m] = p + bias[m];
    }
}

// ---------------- host orchestration ----------------
template <typename T>
static T* symp(const void* sym) {
    void* p = nullptr;
    cudaGetSymbolAddress(&p, sym);
    return (T*)p;
}

extern "C" void kernel_launch(void* const* d_in, const int* in_sizes, int n_in,
                              void* d_out, int out_size) {
    const float* x    = (const float*)d_in[0];
    const int*   esrc = (const int*)d_in[1];
    const int*   edst = (const int*)d_in[2];
    const float* ew   = (const float*)d_in[3];
    const float* gcnW = (const float*)d_in[4];
    const float* gcnb = (const float*)d_in[5];
    const float* lng  = (const float*)d_in[6];
    const float* lnb  = (const float*)d_in[7];
    const float* Wih  = (const float*)d_in[8];
    const float* Whh  = (const float*)d_in[9];
    const float* bih  = (const float*)d_in[10];
    const float* bhh  = (const float*)d_in[11];
    const float* fc1W = (const float*)d_in[12];
    const float* fc1b = (const float*)d_in[13];
    const float* fc2W = (const float*)d_in[14];
    const float* fc2b = (const float*)d_in[15];
    const float* fc3W = (const float*)d_in[16];
    const float* fc3b = (const float*)d_in[17];
    const float* dh1W = (const float*)d_in[18];
    const float* dh1b = (const float*)d_in[19];
    const float* dh2W = (const float*)d_in[20];
    const float* dh2b = (const float*)d_in[21];

    float* outF = (float*)d_out;
    float* outD = outF + (size_t)Nn * Hh;

    float* tmpW  = symp<float>(g_tmpW);
    float* giAll = symp<float>(g_giAll);
    float* gh    = symp<float>(g_gh);
    float* h1    = symp<float>(g_h1);
    float* h2    = symp<float>(g_h2);
    float* f2    = symp<float>(g_f2);
    float* d1    = symp<float>(g_d1);
    float* cb    = symp<float>(g_cb);
    __nv_bfloat16* xs    = symp<__nv_bfloat16>(g_xs);
    __nv_bfloat16* aggA  = symp<__nv_bfloat16>(g_aggA);
    __nv_bfloat16* seqs  = symp<__nv_bfloat16>(g_seqs);
    __nv_bfloat16* hs    = symp<__nv_bfloat16>(g_hs);
    __nv_bfloat16* f1s   = symp<__nv_bfloat16>(g_f1s);
    __nv_bfloat16* gcnWs = symp<__nv_bfloat16>(g_gcnWs);
    __nv_bfloat16* Wihs  = symp<__nv_bfloat16>(g_Wihs);
    __nv_bfloat16* Whhs  = symp<__nv_bfloat16>(g_Whhs);
    __nv_bfloat16* cWs   = symp<__nv_bfloat16>(g_cWs);
    __nv_bfloat16* fc2Ws = symp<__nv_bfloat16>(g_fc2Ws);

    cudaFuncSetAttribute(gemm_mma<0, 0>, cudaFuncAttributeMaxDynamicSharedMemorySize, GEMM_SMEM);
    cudaFuncSetAttribute(gemm_mma<0, 0>, cudaFuncAttributePreferredSharedMemoryCarveout, 100);
    cudaFuncSetAttribute(gemm_mma<1, 0>, cudaFuncAttributeMaxDynamicSharedMemorySize, GEMM_SMEM);
    cudaFuncSetAttribute(gemm_mma<1, 0>, cudaFuncAttributePreferredSharedMemoryCarveout, 100);
    cudaFuncSetAttribute(gemm_mma<1, 3>, cudaFuncAttributeMaxDynamicSharedMemorySize, GEMM_SMEM);
    cudaFuncSetAttribute(gemm_mma<1, 3>, cudaFuncAttributePreferredSharedMemoryCarveout, 100);

    const int TB = 256;
    const int gN = (Nn + TB - 1) / TB;
    const int gE = (Ee + TB - 1) / TB;

    dim3 blk(512);
    const int RB4 = (SN + 255) / 256;   // 313
    const int RB1 = (Nn + 255) / 256;   // 79
    dim3 gGCN(2, RB4);    // M=256
    dim3 gGI(6, RB4);     // M=768
    dim3 gGRU(6, RB1);
    dim3 gHC(2, RB1);     // M=192
    dim3 gH1(1, RB1);     // M=64

    // ---- prologue ordered so the big GCN GEMM stays at launch slot #4 (ncu -s 5) ----
    k_splitT<<<(256 * 256 + TB - 1) / TB, TB>>>(gcnW, gcnWs, 256, 256);                 // #1
    k_split<<<((long)SN * 64 + TB - 1) / TB, TB>>>(x, xs, (long)SN * 64, 64);           // #2
    k_splitT<<<(256 * 256 + TB - 1) / TB, TB>>>(gcnW + 256 * 256,
                                                gcnWs + 256 * 512, 256, 256);           // #3
    gemm_mma<0, 0><<<gGCN, blk, GEMM_SMEM>>>(xs, gcnWs, nullptr, tmpW, nullptr,
                                             SN, 256, 256);                             // #4 <- profile
    k_splitT<<<(256 * 256 + TB - 1) / TB, TB>>>(gcnW + 2 * 256 * 256,
                                                gcnWs + 2 * 256 * 512, 256, 256);
    k_split<<<(768 * 64 + TB - 1) / TB, TB>>>(Wih,  Wihs,  (long)768 * 64, 64);
    k_split<<<(768 * 64 + TB - 1) / TB, TB>>>(Whh,  Whhs,  (long)768 * 64, 64);
    k_split<<<(128 * 64 + TB - 1) / TB, TB>>>(fc1W, cWs, (long)128 * 64, 64);
    k_split<<<(64 * 64 + TB - 1) / TB, TB>>>(dh1W, cWs + (size_t)128 * 512, (long)64 * 64, 64);
    k_split<<<(64 * 32 + TB - 1) / TB, TB>>>(fc2W, fc2Ws, (long)64 * 32, 32);
    cudaMemcpyAsync(cb, fc1b, 128 * sizeof(float), cudaMemcpyDeviceToDevice);
    cudaMemcpyAsync(cb + 128, dh1b, 64 * sizeof(float), cudaMemcpyDeviceToDevice);

    // graph preprocessing -> CSR
    k_init_deg_cnt<<<gN, TB>>>();
    k_edge_deg_cnt<<<gE, TB>>>(edst, ew);
    k_dinv<<<gN, TB>>>();
    k_scan1<<<NB, 256>>>();
    k_scan2<<<1, 128>>>();
    k_scan3<<<NB, 256>>>();
    k_fill_csr<<<gE, TB>>>(esrc, edst, ew);

    // batched GCN stack: aggregation fuses ALL 4 snapshots per block
    k_gcn_agg4<<<Nn, 256>>>(tmpW, gcnb + 0 * Dd, lng + 0 * Dd, lnb + 0 * Dd, aggA);
    gemm_mma<0, 0><<<gGCN, blk, GEMM_SMEM>>>(aggA, gcnWs + 1 * 256 * 512, nullptr, tmpW,
                                             nullptr, SN, 256, 256);
    k_gcn_agg4<<<Nn, 256>>>(tmpW, gcnb + 1 * Dd, lng + 1 * Dd, lnb + 1 * Dd, aggA);
    gemm_mma<0, 0><<<gGCN, blk, GEMM_SMEM>>>(aggA, gcnWs + 2 * 256 * 512, nullptr, tmpW,
                                             nullptr, SN, 256, 256);
    k_gcn_agg4<<<Nn, 256>>>(tmpW, gcnb + 2 * Dd, lng + 2 * Dd, lnb + 2 * Dd, seqs);

    // gi for ALL timesteps in one GEMM
    gemm_mma<0, 0><<<gGI, blk, GEMM_SMEM>>>(seqs, Wihs, bih, giAll, nullptr, SN, 768, 256);

    // GRU recurrence
    const int gCell = (Nn * 64 + TB - 1) / TB;
    k_gru_cell<<<gCell, TB>>>(giAll, gh, bhh, h1, h1, hs, 1);
    for (int t = 1; t < Ss; t++) {
        float* hp = (t & 1) ? h1 : h2;
        float* hn = (t & 1) ? h2 : h1;
        gemm_mma<0, 0><<<gGRU, blk, GEMM_SMEM>>>(hs, Whhs, bhh, gh, nullptr, Nn, 768, 256);
        k_gru_cell<<<gCell, TB>>>(giAll + (size_t)t * Nn * 768, gh, bhh, hp, hn, hs, 0);
    }

    // fused fc1|dh1 GEMM (M=192)
    gemm_mma<1, 3><<<gHC, blk, GEMM_SMEM>>>(hs, cWs, cb, d1, f1s, Nn, 192, 256);
    gemm_mma<1, 0><<<gH1, blk, GEMM_SMEM>>>(f1s, fc2Ws, fc2b, f2, nullptr, Nn, 64, 128);
    k_head5<<<(Nn * 32 + TB - 1) / TB, TB>>>(f2, fc3W, fc3b, outF);
    k_head5<<<(Nn * 32 + TB - 1) / TB, TB>>>(d1, dh2W, dh2b, outD);
}

// round 15
// speedup vs baseline: 1.1501x; 1.1501x over previous
#include <cuda_runtime.h>
#include <cuda_bf16.h>
#include <math.h>
#include <stdint.h>

#define Nn 20000
#define Dd 256
#define Ss 4
#define Ee 320000
#define Hh 5
#define SN (Ss * Nn)
#define NB 79                      // ceil(Nn/256)

// ---------------- scratch (device globals; no allocs allowed) ----------------
__device__ float g_deg[Nn];
__device__ float g_dinv[Nn];
__device__ int   g_cnt[Nn];
__device__ int   g_rowp[Nn + 1];
__device__ int   g_fill[Nn];
__device__ int   g_bsum[NB + 1];
__device__ int   g_boff[NB + 1];
__device__ int   g_csrc[Ee];
__device__ float g_cnorm[Ee];

__device__ float g_tmpW[SN * Dd];
__device__ float g_giAll[SN * 3 * Dd];
__device__ float g_gh[Nn * 3 * Dd];
__device__ float g_h1[Nn * Dd];
__device__ float g_h2[Nn * Dd];
__device__ float g_f2[Nn * 64];
__device__ float g_d1[Nn * 64];
__device__ float g_cb[192];

// split-bf16 activations: layout [rows, 2K] = [hi | lo]
__device__ __nv_bfloat16 g_xs[SN * 512];
__device__ __nv_bfloat16 g_aggA[SN * 512];
__device__ __nv_bfloat16 g_seqs[SN * 512];
__device__ __nv_bfloat16 g_hs[Nn * 512];
__device__ __nv_bfloat16 g_f1s[Nn * 256];

// split-bf16 weights: [M, 2K]
__device__ __nv_bfloat16 g_gcnWs[3 * 256 * 512];
__device__ __nv_bfloat16 g_Wihs[768 * 512];
__device__ __nv_bfloat16 g_Whhs[768 * 512];
__device__ __nv_bfloat16 g_cWs[192 * 512];
__device__ __nv_bfloat16 g_fc2Ws[64 * 256];

// ---------------- helpers ----------------
__device__ __forceinline__ void split_write(float v, __nv_bfloat16* hi, __nv_bfloat16* lo) {
    __nv_bfloat16 h = __float2bfloat16(v);
    *hi = h;
    *lo = __float2bfloat16(v - __bfloat162float(h));
}
__device__ __forceinline__ void split_write2(float v0, float v1,
                                             __nv_bfloat16* hi, __nv_bfloat16* lo) {
    __nv_bfloat16 h0 = __float2bfloat16(v0), h1 = __float2bfloat16(v1);
    __nv_bfloat162 hh; hh.x = h0; hh.y = h1;
    *reinterpret_cast<__nv_bfloat162*>(hi) = hh;
    __nv_bfloat162 ll;
    ll.x = __float2bfloat16(v0 - __bfloat162float(h0));
    ll.y = __float2bfloat16(v1 - __bfloat162float(h1));
    *reinterpret_cast<__nv_bfloat162*>(lo) = ll;
}
__device__ __forceinline__ void split_write4(float4 v, __nv_bfloat16* hi, __nv_bfloat16* lo) {
    split_write2(v.x, v.y, hi, lo);
    split_write2(v.z, v.w, hi + 2, lo + 2);
}
__device__ __forceinline__ void ldsm4(uint32_t* r, uint32_t addr) {
    asm volatile("ldmatrix.sync.aligned.m8n8.x4.shared.b16 {%0,%1,%2,%3}, [%4];"
                 : "=r"(r[0]), "=r"(r[1]), "=r"(r[2]), "=r"(r[3]) : "r"(addr));
}
__device__ __forceinline__ void mma16816(float* c, const uint32_t* a, const uint32_t* b) {
    asm volatile(
        "mma.sync.aligned.m16n8k16.row.col.f32.bf16.bf16.f32 "
        "{%0,%1,%2,%3}, {%4,%5,%6,%7}, {%8,%9}, {%0,%1,%2,%3};"
        : "+f"(c[0]), "+f"(c[1]), "+f"(c[2]), "+f"(c[3])
        : "r"(a[0]), "r"(a[1]), "r"(a[2]), "r"(a[3]), "r"(b[0]), "r"(b[1]));
}
__device__ __forceinline__ void cpa16z(uint32_t dst, const void* src, int sz) {
    asm volatile("cp.async.cg.shared.global [%0], [%1], 16, %2;"
                 :: "r"(dst), "l"(src), "r"(sz));
}
__device__ __forceinline__ float gelu1(float v) {
    return 0.5f * v * (1.0f + erff(v * 0.7071067811865475f));
}

// ---------------- graph preprocessing ----------------
__global__ void k_init_deg_cnt() {
    int i = blockIdx.x * blockDim.x + threadIdx.x;
    if (i < Nn) { g_deg[i] = 1.0f; g_cnt[i] = 0; }
}
__global__ void k_edge_deg_cnt(const int* __restrict__ dst, const float* __restrict__ w) {
    int e = blockIdx.x * blockDim.x + threadIdx.x;
    if (e < Ee) {
        int t = dst[e];
        atomicAdd(&g_deg[t], w[e]);
        atomicAdd(&g_cnt[t], 1);
    }
}
__global__ void k_dinv() {
    int i = blockIdx.x * blockDim.x + threadIdx.x;
    if (i < Nn) g_dinv[i] = rsqrtf(g_deg[i]);
}
__global__ void __launch_bounds__(256) k_scan1() {
    __shared__ int wsum[8];
    int i = blockIdx.x * 256 + threadIdx.x;
    int lane = threadIdx.x & 31, wd = threadIdx.x >> 5;
    int v = (i < Nn) ? g_cnt[i] : 0;
    int x = v;
#pragma unroll
    for (int o = 1; o < 32; o <<= 1) {
        int y = __shfl_up_sync(0xffffffffu, x, o);
        if (lane >= o) x += y;
    }
    if (lane == 31) wsum[wd] = x;
    __syncthreads();
    if (threadIdx.x == 0) {
        int acc = 0;
#pragma unroll
        for (int w = 0; w < 8; w++) { int t = wsum[w]; wsum[w] = acc; acc += t; }
        g_bsum[blockIdx.x] = acc;
    }
    __syncthreads();
    if (i < Nn) g_rowp[i] = wsum[wd] + x - v;
}
__global__ void k_scan2() {
    int t = threadIdx.x;
    __shared__ int sh[NB];
    if (t < NB) sh[t] = g_bsum[t];
    __syncthreads();
    if (t == 0) {
        int acc = 0;
        for (int b = 0; b < NB; b++) { int v = sh[b]; g_boff[b] = acc; acc += v; }
        g_rowp[Nn] = acc;
    }
}
__global__ void __launch_bounds__(256) k_scan3() {
    int i = blockIdx.x * 256 + threadIdx.x;
    if (i < Nn) {
        int r = g_rowp[i] + g_boff[blockIdx.x];
        g_rowp[i] = r;
        g_fill[i] = r;
    }
}
__global__ void k_fill_csr(const int* __restrict__ src, const int* __restrict__ dst,
                           const float* __restrict__ w) {
    int e = blockIdx.x * blockDim.x + threadIdx.x;
    if (e < Ee) {
        int s = src[e], t = dst[e];
        int pos = atomicAdd(&g_fill[t], 1);
        g_csrc[pos]  = s;
        g_cnorm[pos] = g_dinv[s] * w[e] * g_dinv[t];
    }
}

// ---------------- split conversion kernels ----------------
__global__ void k_split(const float* __restrict__ in, __nv_bfloat16* __restrict__ out,
                        long total4, int K4) {
    long idx = (long)blockIdx.x * blockDim.x + threadIdx.x;
    if (idx >= total4) return;
    long r = idx / K4;
    int  c = (int)(idx - r * K4) * 4;
    int  K = K4 * 4;
    float4 v = *reinterpret_cast<const float4*>(in + r * K + c);
    split_write4(v, &out[r * 2 * K + c], &out[r * 2 * K + K + c]);
}
__global__ void k_splitT(const float* __restrict__ in, __nv_bfloat16* __restrict__ out,
                         int Kd, int Md) {
    long idx = (long)blockIdx.x * blockDim.x + threadIdx.x;
    if (idx >= (long)Kd * Md) return;
    int k = (int)(idx / Md);
    int m = (int)(idx - (long)k * Md);
    float v = in[idx];
    split_write(v, &out[(long)m * 2 * Kd + k], &out[(long)m * 2 * Kd + Kd + k]);
}

// ---- bf16 mma.sync GEMM: R13 proven core (128x128, 256 thr, 2 CTA/SM) ----
// C[R,M] = A[R,K] @ B[M,K]^T; A/B split: [rows, 2K] = [hi | lo].
// Hoisted loader: thread -> (array, 8-row span, seg); merged 3-term mainloop.
#define SROW2 40
#define ARR_B (128 * SROW2 * 2)
#define STAGE_B (4 * ARR_B)
#define GEMM_SMEM (2 * STAGE_B)
template <int ACT, int MODE>
__global__ void __launch_bounds__(256, 2)
gemm_mma(const __nv_bfloat16* __restrict__ A, const __nv_bfloat16* __restrict__ B,
         const float* __restrict__ bias, float* __restrict__ outF,
         __nv_bfloat16* __restrict__ outS, int R, int M, int K) {
    extern __shared__ __align__(16) __nv_bfloat16 smg[];
    const uint32_t sbase = (uint32_t)__cvta_generic_to_shared(smg);

    const int tid  = threadIdx.x;
    const int lane = tid & 31, wid = tid >> 5;
    const int wm = wid & 1;
    const int wn = wid >> 1;
    const long rowA = (long)blockIdx.y * 128;
    const long colB = (long)blockIdx.x * 128;
    const int K2 = 2 * K;
    const int NC = K >> 5;

    // hoisted loader state: arr = tid>>6 (0=Ah 1=Al 2=Bh 3=Bl)
    const int arrid = tid >> 6;
    const int l6    = tid & 63;
    const int row0  = (l6 >> 2) * 8;
    const int seg   = l6 & 3;
    const bool isA  = arrid < 2;
    const long rb   = (isA ? rowA : colB) + row0;
    const int  lim  = isA ? R : M;
    int szs[8];
#pragma unroll
    for (int u = 0; u < 8; u++) szs[u] = (rb + u < lim) ? 16 : 0;
    const __nv_bfloat16* sp = (isA ? A : B) + rb * (long)K2 +
                              ((arrid & 1) ? K : 0) + seg * 8;
    const uint32_t dstb = (uint32_t)arrid * ARR_B +
                          (uint32_t)(row0 * SROW2 + seg * 8) * 2;

    float acc[4][4][4];
#pragma unroll
    for (int i = 0; i < 4; i++)
#pragma unroll
        for (int j = 0; j < 4; j++)
#pragma unroll
            for (int k = 0; k < 4; k++) acc[i][j][k] = 0.0f;

    auto ld_chunk = [&](int c, int buf) {
        uint32_t stg = sbase + (uint32_t)buf * STAGE_B + dstb;
        const __nv_bfloat16* s = sp + (long)c * 32;
#pragma unroll
        for (int u = 0; u < 8; u++)
            cpa16z(stg + (uint32_t)(u * SROW2 * 2), s + (long)u * K2, szs[u]);
        asm volatile("cp.async.commit_group;" ::: "memory");
    };

    ld_chunk(0, 0);

    const uint32_t aOffC = ((uint32_t)(wm * 64 + (lane & 15)) * SROW2 + (lane >> 4) * 8) * 2;
    const uint32_t bOffC = ((uint32_t)(wn * 32 + ((lane >> 4) & 1) * 8 + (lane & 7)) * SROW2 +
                            ((lane >> 3) & 1) * 8) * 2;

    for (int c = 0; c < NC; c++) {
        int buf = c & 1;
        if (c + 1 < NC) {
            ld_chunk(c + 1, buf ^ 1);
            asm volatile("cp.async.wait_group 1;" ::: "memory");
        } else {
            asm volatile("cp.async.wait_group 0;" ::: "memory");
        }
        __syncthreads();
        uint32_t stg = sbase + (uint32_t)buf * STAGE_B;
        uint32_t ah = stg + aOffC;
        uint32_t al = ah + ARR_B;
        uint32_t bh = stg + 2 * ARR_B + bOffC;
        uint32_t bl = bh + ARR_B;
#pragma unroll
        for (int ks = 0; ks < 2; ks++) {
            uint32_t koff = (uint32_t)(ks * 16) * 2;
            uint32_t bhf[2][4], blf[2][4];
#pragma unroll
            for (int nt = 0; nt < 2; nt++) {
                ldsm4(bhf[nt], bh + (uint32_t)(nt * 16 * SROW2) * 2 + koff);
                ldsm4(blf[nt], bl + (uint32_t)(nt * 16 * SROW2) * 2 + koff);
            }
#pragma unroll
            for (int half = 0; half < 2; half++) {
                uint32_t ahf[2][4], alf[2][4];
#pragma unroll
                for (int m2 = 0; m2 < 2; m2++) {
                    int mt = half * 2 + m2;
                    ldsm4(ahf[m2], ah + (uint32_t)(mt * 16 * SROW2) * 2 + koff);
                    ldsm4(alf[m2], al + (uint32_t)(mt * 16 * SROW2) * 2 + koff);
                }
#pragma unroll
                for (int m2 = 0; m2 < 2; m2++)
#pragma unroll
                    for (int j = 0; j < 4; j++)
                        mma16816(acc[half * 2 + m2][j], ahf[m2], &bhf[j >> 1][(j & 1) * 2]);
#pragma unroll
                for (int m2 = 0; m2 < 2; m2++)
#pragma unroll
                    for (int j = 0; j < 4; j++)
                        mma16816(acc[half * 2 + m2][j], ahf[m2], &blf[j >> 1][(j & 1) * 2]);
#pragma unroll
                for (int m2 = 0; m2 < 2; m2++)
#pragma unroll
                    for (int j = 0; j < 4; j++)
                        mma16816(acc[half * 2 + m2][j], alf[m2], &bhf[j >> 1][(j & 1) * 2]);
            }
        }
        __syncthreads();
    }

    // vectorized epilogue
#pragma unroll
    for (int mt = 0; mt < 4; mt++) {
        long r0e = rowA + wm * 64 + mt * 16 + (lane >> 2);
#pragma unroll
        for (int j = 0; j < 4; j++) {
            int col0 = (int)colB + wn * 32 + j * 8 + (lane & 3) * 2;
            if (col0 >= M) continue;
            float2 b2 = make_float2(0.f, 0.f);
            if (bias) b2 = *reinterpret_cast<const float2*>(bias + col0);
#pragma unroll
            for (int half = 0; half < 2; half++) {
                long r = r0e + half * 8;
                if (r >= R) continue;
                float v0 = acc[mt][j][half * 2 + 0] + b2.x;
                float v1 = acc[mt][j][half * 2 + 1] + b2.y;
                if (ACT) { v0 = gelu1(v0); v1 = gelu1(v1); }
                if (MODE == 0) {
                    *reinterpret_cast<float2*>(outF + r * (long)M + col0) = make_float2(v0, v1);
                } else {   // MODE 3: fused fc1|dh1
                    if (col0 < 128)
                        split_write2(v0, v1, &outS[r * 256 + col0], &outS[r * 256 + 128 + col0]);
                    else
                        *reinterpret_cast<float2*>(outF + r * 64 + (col0 - 128)) =
                            make_float2(v0, v1);
                }
            }
        }
    }
}

// ---- GCN aggregate, 4 snapshots x 64-thread groups, float4 gathers (R14 winner) ----
__global__ void __launch_bounds__(256)
k_gcn_agg4(const float* __restrict__ hW,
           const float* __restrict__ bias, const float* __restrict__ g,
           const float* __restrict__ b, __nv_bfloat16* __restrict__ out) {
    const int t  = blockIdx.x;
    const int si = threadIdx.x >> 6;       // snapshot group 0..3
    const int l6 = threadIdx.x & 63;
    const int d4 = l6 << 2;                // feature base (float4)
    const float di = g_dinv[t];
    const float di2 = di * di;
    const float* base = hW + (size_t)si * Nn * Dd;

    float4 acc = *reinterpret_cast<const float4*>(base + (size_t)t * Dd + d4);
    acc.x *= di2; acc.y *= di2; acc.z *= di2; acc.w *= di2;

    int e0 = g_rowp[t], e1 = g_rowp[t + 1];
#pragma unroll 2
    for (int e = e0; e < e1; e++) {
        int s = __ldg(&g_csrc[e]);
        float nm = __ldg(&g_cnorm[e]);
        float4 v = *reinterpret_cast<const float4*>(base + (size_t)s * Dd + d4);
        acc.x += nm * v.x; acc.y += nm * v.y; acc.z += nm * v.z; acc.w += nm * v.w;
    }
    float4 bb = *reinterpret_cast<const float4*>(bias + d4);
    acc.x += bb.x; acc.y += bb.y; acc.z += bb.z; acc.w += bb.w;

    // LN over this group's 256 values (64 threads x 4)
    __shared__ float rs[8], rq[8];
    __shared__ float mvm[Ss], mvr[Ss];
    float sum = acc.x + acc.y + acc.z + acc.w;
    float sq  = acc.x * acc.x + acc.y * acc.y + acc.z * acc.z + acc.w * acc.w;
    const int lane = threadIdx.x & 31, wd = threadIdx.x >> 5;
#pragma unroll
    for (int o = 16; o; o >>= 1) {
        sum += __shfl_down_sync(0xffffffffu, sum, o);
        sq  += __shfl_down_sync(0xffffffffu, sq, o);
    }
    if (lane == 0) { rs[wd] = sum; rq[wd] = sq; }
    __syncthreads();
    if (threadIdx.x < Ss) {
        float ss = rs[2 * threadIdx.x] + rs[2 * threadIdx.x + 1];
        float qq = rq[2 * threadIdx.x] + rq[2 * threadIdx.x + 1];
        float m = ss * (1.0f / 256.0f);
        float var = qq * (1.0f / 256.0f) - m * m;
        mvm[threadIdx.x] = m;
        mvr[threadIdx.x] = rsqrtf(var + 1e-5f);
    }
    __syncthreads();
    const float m = mvm[si], rstd = mvr[si];
    float4 gg = *reinterpret_cast<const float4*>(g + d4);
    float4 b2 = *reinterpret_cast<const float4*>(b + d4);
    float4 val;
    val.x = fmaxf((acc.x - m) * rstd * gg.x + b2.x, 0.0f);
    val.y = fmaxf((acc.y - m) * rstd * gg.y + b2.y, 0.0f);
    val.z = fmaxf((acc.z - m) * rstd * gg.z + b2.z, 0.0f);
    val.w = fmaxf((acc.w - m) * rstd * gg.w + b2.w, 0.0f);
    __nv_bfloat16* o = out + ((size_t)si * Nn + t) * 512;
    split_write4(val, &o[d4], &o[256 + d4]);
}

// ---------------- GRU cell, float4 vectorized ----------------
__global__ void k_gru_cell(const float* __restrict__ gi, const float* __restrict__ gh,
                           const float* __restrict__ bhh, const float* __restrict__ hprev,
                           float* __restrict__ hnew, __nv_bfloat16* __restrict__ hs,
                           int first) {
    int idx = blockIdx.x * blockDim.x + threadIdx.x;
    if (idx >= Nn * 64) return;
    int n = idx >> 6, d = (idx & 63) << 2;
    const float* gir = gi + (size_t)n * 768;
    float4 ir = *reinterpret_cast<const float4*>(gir + d);
    float4 iz = *reinterpret_cast<const float4*>(gir + 256 + d);
    float4 ig = *reinterpret_cast<const float4*>(gir + 512 + d);
    float4 hr, hz, hg, hp;
    if (first) {
        hr = *reinterpret_cast<const float4*>(bhh + d);
        hz = *reinterpret_cast<const float4*>(bhh + 256 + d);
        hg = *reinterpret_cast<const float4*>(bhh + 512 + d);
        hp = make_float4(0.f, 0.f, 0.f, 0.f);
    } else {
        const float* ghr = gh + (size_t)n * 768;
        hr = *reinterpret_cast<const float4*>(ghr + d);
        hz = *reinterpret_cast<const float4*>(ghr + 256 + d);
        hg = *reinterpret_cast<const float4*>(ghr + 512 + d);
        hp = *reinterpret_cast<const float4*>(hprev + (size_t)n * 256 + d);
    }
    float4 v;
#define GRU1(c) { \
        float r = 1.0f / (1.0f + expf(-(ir.c + hr.c))); \
        float z = 1.0f / (1.0f + expf(-(iz.c + hz.c))); \
        float ng = tanhf(ig.c + r * hg.c); \
        v.c = (1.0f - z) * ng + z * hp.c; }
    GRU1(x) GRU1(y) GRU1(z) GRU1(w)
#undef GRU1
    *reinterpret_cast<float4*>(hnew + (size_t)n * 256 + d) = v;
    split_write4(v, &hs[(size_t)n * 512 + d], &hs[(size_t)n * 512 + 256 + d]);
}

// ---------------- tiny head GEMM ----------------
__global__ void __launch_bounds__(256)
k_head5(const float* __restrict__ in, const float* __restrict__ W,
        const float* __restrict__ bias, float* __restrict__ out) {
    __shared__ float sW[5 * 64];
    for (int i = threadIdx.x; i < 5 * 64; i += blockDim.x) sW[i] = W[i];
    __syncthreads();
    int gw = (blockIdx.x * blockDim.x + threadIdx.x) >> 5;
    int lane = threadIdx.x & 31;
    if (gw >= Nn) return;
    float x0 = in[(size_t)gw * 64 + lane];
    float x1 = in[(size_t)gw * 64 + 32 + lane];
#pragma unroll
    for (int m = 0; m < 5; m++) {
        float p = x0 * sW[m * 64 + lane] + x1 * sW[m * 64 + 32 + lane];
#pragma unroll
        for (int o = 16; o; o >>= 1) p += __shfl_down_sync(0xffffffffu, p, o);
        if (lane == 0) out[(size_t)gw * 5 + m] = p + bias[m];
    }
}

// ---------------- host orchestration ----------------
template <typename T>
static T* symp(const void* sym) {
    void* p = nullptr;
    cudaGetSymbolAddress(&p, sym);
    return (T*)p;
}

extern "C" void kernel_launch(void* const* d_in, const int* in_sizes, int n_in,
                              void* d_out, int out_size) {
    const float* x    = (const float*)d_in[0];
    const int*   esrc = (const int*)d_in[1];
    const int*   edst = (const int*)d_in[2];
    const float* ew   = (const float*)d_in[3];
    const float* gcnW = (const float*)d_in[4];
    const float* gcnb = (const float*)d_in[5];
    const float* lng  = (const float*)d_in[6];
    const float* lnb  = (const float*)d_in[7];
    const float* Wih  = (const float*)d_in[8];
    const float* Whh  = (const float*)d_in[9];
    const float* bih  = (const float*)d_in[10];
    const float* bhh  = (const float*)d_in[11];
    const float* fc1W = (const float*)d_in[12];
    const float* fc1b = (const float*)d_in[13];
    const float* fc2W = (const float*)d_in[14];
    const float* fc2b = (const float*)d_in[15];
    const float* fc3W = (const float*)d_in[16];
    const float* fc3b = (const float*)d_in[17];
    const float* dh1W = (const float*)d_in[18];
    const float* dh1b = (const float*)d_in[19];
    const float* dh2W = (const float*)d_in[20];
    const float* dh2b = (const float*)d_in[21];

    float* outF = (float*)d_out;
    float* outD = outF + (size_t)Nn * Hh;

    float* tmpW  = symp<float>(g_tmpW);
    float* giAll = symp<float>(g_giAll);
    float* gh    = symp<float>(g_gh);
    float* h1    = symp<float>(g_h1);
    float* h2    = symp<float>(g_h2);
    float* f2    = symp<float>(g_f2);
    float* d1    = symp<float>(g_d1);
    float* cb    = symp<float>(g_cb);
    __nv_bfloat16* xs    = symp<__nv_bfloat16>(g_xs);
    __nv_bfloat16* aggA  = symp<__nv_bfloat16>(g_aggA);
    __nv_bfloat16* seqs  = symp<__nv_bfloat16>(g_seqs);
    __nv_bfloat16* hs    = symp<__nv_bfloat16>(g_hs);
    __nv_bfloat16* f1s   = symp<__nv_bfloat16>(g_f1s);
    __nv_bfloat16* gcnWs = symp<__nv_bfloat16>(g_gcnWs);
    __nv_bfloat16* Wihs  = symp<__nv_bfloat16>(g_Wihs);
    __nv_bfloat16* Whhs  = symp<__nv_bfloat16>(g_Whhs);
    __nv_bfloat16* cWs   = symp<__nv_bfloat16>(g_cWs);
    __nv_bfloat16* fc2Ws = symp<__nv_bfloat16>(g_fc2Ws);

    cudaFuncSetAttribute(gemm_mma<0, 0>, cudaFuncAttributeMaxDynamicSharedMemorySize, GEMM_SMEM);
    cudaFuncSetAttribute(gemm_mma<0, 0>, cudaFuncAttributePreferredSharedMemoryCarveout, 100);
    cudaFuncSetAttribute(gemm_mma<1, 0>, cudaFuncAttributeMaxDynamicSharedMemorySize, GEMM_SMEM);
    cudaFuncSetAttribute(gemm_mma<1, 0>, cudaFuncAttributePreferredSharedMemoryCarveout, 100);
    cudaFuncSetAttribute(gemm_mma<1, 3>, cudaFuncAttributeMaxDynamicSharedMemorySize, GEMM_SMEM);
    cudaFuncSetAttribute(gemm_mma<1, 3>, cudaFuncAttributePreferredSharedMemoryCarveout, 100);

    const int TB = 256;
    const int gN = (Nn + TB - 1) / TB;
    const int gE = (Ee + TB - 1) / TB;

    dim3 blk(256);
    const int RB4 = (SN + 127) / 128;   // 625
    const int RB1 = (Nn + 127) / 128;   // 157
    dim3 gGCN(2, RB4);
    dim3 gGI(6, RB4);
    dim3 gGRU(6, RB1);
    dim3 gHC(2, RB1);
    dim3 gH1(1, RB1);

    // ---- prologue ordered so the big GCN GEMM stays at launch slot #4 (ncu -s 5) ----
    k_splitT<<<(256 * 256 + TB - 1) / TB, TB>>>(gcnW, gcnWs, 256, 256);                 // #1
    k_split<<<((long)SN * 64 + TB - 1) / TB, TB>>>(x, xs, (long)SN * 64, 64);           // #2
    k_splitT<<<(256 * 256 + TB - 1) / TB, TB>>>(gcnW + 256 * 256,
                                                gcnWs + 256 * 512, 256, 256);           // #3
    gemm_mma<0, 0><<<gGCN, blk, GEMM_SMEM>>>(xs, gcnWs, nullptr, tmpW, nullptr,
                                             SN, 256, 256);                             // #4 <- profile
    k_splitT<<<(256 * 256 + TB - 1) / TB, TB>>>(gcnW + 2 * 256 * 256,
                                                gcnWs + 2 * 256 * 512, 256, 256);
    k_split<<<(768 * 64 + TB - 1) / TB, TB>>>(Wih,  Wihs,  (long)768 * 64, 64);
    k_split<<<(768 * 64 + TB - 1) / TB, TB>>>(Whh,  Whhs,  (long)768 * 64, 64);
    k_split<<<(128 * 64 + TB - 1) / TB, TB>>>(fc1W, cWs, (long)128 * 64, 64);
    k_split<<<(64 * 64 + TB - 1) / TB, TB>>>(dh1W, cWs + (size_t)128 * 512, (long)64 * 64, 64);
    k_split<<<(64 * 32 + TB - 1) / TB, TB>>>(fc2W, fc2Ws, (long)64 * 32, 32);
    cudaMemcpyAsync(cb, fc1b, 128 * sizeof(float), cudaMemcpyDeviceToDevice);
    cudaMemcpyAsync(cb + 128, dh1b, 64 * sizeof(float), cudaMemcpyDeviceToDevice);

    // graph preprocessing -> CSR
    k_init_deg_cnt<<<gN, TB>>>();
    k_edge_deg_cnt<<<gE, TB>>>(edst, ew);
    k_dinv<<<gN, TB>>>();
    k_scan1<<<NB, 256>>>();
    k_scan2<<<1, 128>>>();
    k_scan3<<<NB, 256>>>();
    k_fill_csr<<<gE, TB>>>(esrc, edst, ew);

    // batched GCN stack: aggregation fuses ALL 4 snapshots per block
    k_gcn_agg4<<<Nn, 256>>>(tmpW, gcnb + 0 * Dd, lng + 0 * Dd, lnb + 0 * Dd, aggA);
    gemm_mma<0, 0><<<gGCN, blk, GEMM_SMEM>>>(aggA, gcnWs + 1 * 256 * 512, nullptr, tmpW,
                                             nullptr, SN, 256, 256);
    k_gcn_agg4<<<Nn, 256>>>(tmpW, gcnb + 1 * Dd, lng + 1 * Dd, lnb + 1 * Dd, aggA);
    gemm_mma<0, 0><<<gGCN, blk, GEMM_SMEM>>>(aggA, gcnWs + 2 * 256 * 512, nullptr, tmpW,
                                             nullptr, SN, 256, 256);
    k_gcn_agg4<<<Nn, 256>>>(tmpW, gcnb + 2 * Dd, lng + 2 * Dd, lnb + 2 * Dd, seqs);

    // gi for ALL timesteps in one GEMM
    gemm_mma<0, 0><<<gGI, blk, GEMM_SMEM>>>(seqs, Wihs, bih, giAll, nullptr, SN, 768, 256);

    // GRU recurrence
    const int gCell = (Nn * 64 + TB - 1) / TB;
    k_gru_cell<<<gCell, TB>>>(giAll, gh, bhh, h1, h1, hs, 1);
    for (int t = 1; t < Ss; t++) {
        float* hp = (t & 1) ? h1 : h2;
        float* hn = (t & 1) ? h2 : h1;
        gemm_mma<0, 0><<<gGRU, blk, GEMM_SMEM>>>(hs, Whhs, bhh, gh, nullptr, Nn, 768, 256);
        k_gru_cell<<<gCell, TB>>>(giAll + (size_t)t * Nn * 768, gh, bhh, hp, hn, hs, 0);
    }

    // fused fc1|dh1 GEMM (M=192)
    gemm_mma<1, 3><<<gHC, blk, GEMM_SMEM>>>(hs, cWs, cb, d1, f1s, Nn, 192, 256);
    gemm_mma<1, 0><<<gH1, blk, GEMM_SMEM>>>(f1s, fc2Ws, fc2b, f2, nullptr, Nn, 64, 128);
    k_head5<<<(Nn * 32 + TB - 1) / TB, TB>>>(f2, fc3W, fc3b, outF);
    k_head5<<<(Nn * 32 + TB - 1) / TB, TB>>>(d1, dh2W, dh2b, outD);
}

// round 16
// speedup vs baseline: 1.1537x; 1.0031x over previous
#include <cuda_runtime.h>
#include <cuda_bf16.h>
#include <math.h>
#include <stdint.h>

#define Nn 20000
#define Dd 256
#define Ss 4
#define Ee 320000
#define Hh 5
#define SN (Ss * Nn)
#define NB 79                      // ceil(Nn/256)

// ---------------- scratch (device globals; no allocs allowed) ----------------
__device__ float g_deg[Nn];
__device__ float g_dinv[Nn];
__device__ int   g_cnt[Nn];
__device__ int   g_rowp[Nn + 1];
__device__ int   g_fill[Nn];
__device__ int   g_bsum[NB + 1];
__device__ int   g_boff[NB + 1];
__device__ int   g_csrc[Ee];
__device__ float g_cnorm[Ee];

__device__ float g_tmpW[SN * Dd];
__device__ float g_giAll[SN * 3 * Dd];
__device__ float g_gh[Nn * 3 * Dd];
__device__ float g_h1[Nn * Dd];
__device__ float g_h2[Nn * Dd];
__device__ float g_f2[Nn * 64];
__device__ float g_d1[Nn * 64];
__device__ float g_cb[192];

// split-bf16 activations: layout [rows, 2K] = [hi | lo]
__device__ __nv_bfloat16 g_xs[SN * 512];
__device__ __nv_bfloat16 g_aggA[SN * 512];
__device__ __nv_bfloat16 g_seqs[SN * 512];
__device__ __nv_bfloat16 g_hs[Nn * 512];
__device__ __nv_bfloat16 g_f1s[Nn * 256];

// split-bf16 weights: [M, 2K]
__device__ __nv_bfloat16 g_gcnWs[3 * 256 * 512];
__device__ __nv_bfloat16 g_Wihs[768 * 512];
__device__ __nv_bfloat16 g_Whhs[768 * 512];
__device__ __nv_bfloat16 g_cWs[192 * 512];
__device__ __nv_bfloat16 g_fc2Ws[64 * 256];

// ---------------- helpers ----------------
__device__ __forceinline__ void split_write(float v, __nv_bfloat16* hi, __nv_bfloat16* lo) {
    __nv_bfloat16 h = __float2bfloat16(v);
    *hi = h;
    *lo = __float2bfloat16(v - __bfloat162float(h));
}
__device__ __forceinline__ void split_write2(float v0, float v1,
                                             __nv_bfloat16* hi, __nv_bfloat16* lo) {
    __nv_bfloat16 h0 = __float2bfloat16(v0), h1 = __float2bfloat16(v1);
    __nv_bfloat162 hh; hh.x = h0; hh.y = h1;
    *reinterpret_cast<__nv_bfloat162*>(hi) = hh;
    __nv_bfloat162 ll;
    ll.x = __float2bfloat16(v0 - __bfloat162float(h0));
    ll.y = __float2bfloat16(v1 - __bfloat162float(h1));
    *reinterpret_cast<__nv_bfloat162*>(lo) = ll;
}
__device__ __forceinline__ void split_write4(float4 v, __nv_bfloat16* hi, __nv_bfloat16* lo) {
    split_write2(v.x, v.y, hi, lo);
    split_write2(v.z, v.w, hi + 2, lo + 2);
}
__device__ __forceinline__ void ldsm4(uint32_t* r, uint32_t addr) {
    asm volatile("ldmatrix.sync.aligned.m8n8.x4.shared.b16 {%0,%1,%2,%3}, [%4];"
                 : "=r"(r[0]), "=r"(r[1]), "=r"(r[2]), "=r"(r[3]) : "r"(addr));
}
__device__ __forceinline__ void mma16816(float* c, const uint32_t* a, const uint32_t* b) {
    asm volatile(
        "mma.sync.aligned.m16n8k16.row.col.f32.bf16.bf16.f32 "
        "{%0,%1,%2,%3}, {%4,%5,%6,%7}, {%8,%9}, {%0,%1,%2,%3};"
        : "+f"(c[0]), "+f"(c[1]), "+f"(c[2]), "+f"(c[3])
        : "r"(a[0]), "r"(a[1]), "r"(a[2]), "r"(a[3]), "r"(b[0]), "r"(b[1]));
}
__device__ __forceinline__ void cpa16z(uint32_t dst, const void* src, int sz) {
    asm volatile("cp.async.cg.shared.global [%0], [%1], 16, %2;"
                 :: "r"(dst), "l"(src), "r"(sz));
}
__device__ __forceinline__ float gelu1(float v) {
    return 0.5f * v * (1.0f + erff(v * 0.7071067811865475f));
}

// ---------------- graph preprocessing ----------------
__global__ void k_init_deg_cnt() {
    int i = blockIdx.x * blockDim.x + threadIdx.x;
    if (i < Nn) { g_deg[i] = 1.0f; g_cnt[i] = 0; }
}
__global__ void k_edge_deg_cnt(const int* __restrict__ dst, const float* __restrict__ w) {
    int e = blockIdx.x * blockDim.x + threadIdx.x;
    if (e < Ee) {
        int t = dst[e];
        atomicAdd(&g_deg[t], w[e]);
        atomicAdd(&g_cnt[t], 1);
    }
}
// scan pass 1 (dinv fused: g_deg is final after edge_deg)
__global__ void __launch_bounds__(256) k_scan1() {
    __shared__ int wsum[8];
    int i = blockIdx.x * 256 + threadIdx.x;
    int lane = threadIdx.x & 31, wd = threadIdx.x >> 5;
    if (i < Nn) g_dinv[i] = rsqrtf(g_deg[i]);
    int v = (i < Nn) ? g_cnt[i] : 0;
    int x = v;
#pragma unroll
    for (int o = 1; o < 32; o <<= 1) {
        int y = __shfl_up_sync(0xffffffffu, x, o);
        if (lane >= o) x += y;
    }
    if (lane == 31) wsum[wd] = x;
    __syncthreads();
    if (threadIdx.x == 0) {
        int acc = 0;
#pragma unroll
        for (int w = 0; w < 8; w++) { int t = wsum[w]; wsum[w] = acc; acc += t; }
        g_bsum[blockIdx.x] = acc;
    }
    __syncthreads();
    if (i < Nn) g_rowp[i] = wsum[wd] + x - v;
}
__global__ void k_scan2() {
    int t = threadIdx.x;
    __shared__ int sh[NB];
    if (t < NB) sh[t] = g_bsum[t];
    __syncthreads();
    if (t == 0) {
        int acc = 0;
        for (int b = 0; b < NB; b++) { int v = sh[b]; g_boff[b] = acc; acc += v; }
        g_rowp[Nn] = acc;
    }
}
__global__ void __launch_bounds__(256) k_scan3() {
    int i = blockIdx.x * 256 + threadIdx.x;
    if (i < Nn) {
        int r = g_rowp[i] + g_boff[blockIdx.x];
        g_rowp[i] = r;
        g_fill[i] = r;
    }
}
__global__ void k_fill_csr(const int* __restrict__ src, const int* __restrict__ dst,
                           const float* __restrict__ w) {
    int e = blockIdx.x * blockDim.x + threadIdx.x;
    if (e < Ee) {
        int s = src[e], t = dst[e];
        int pos = atomicAdd(&g_fill[t], 1);
        g_csrc[pos]  = s;
        g_cnorm[pos] = g_dinv[s] * w[e] * g_dinv[t];
    }
}

// ---------------- split conversion ----------------
// activation split (vectorized, 4 elems/thread)
__global__ void k_split(const float* __restrict__ in, __nv_bfloat16* __restrict__ out,
                        long total4, int K4) {
    long idx = (long)blockIdx.x * blockDim.x + threadIdx.x;
    if (idx >= total4) return;
    long r = idx / K4;
    int  c = (int)(idx - r * K4) * 4;
    int  K = K4 * 4;
    float4 v = *reinterpret_cast<const float4*>(in + r * K + c);
    split_write4(v, &out[r * 2 * K + c], &out[r * 2 * K + K + c]);
}
// ONE launch for ALL weight prep (splits + transposed splits + bias concat)
__global__ void __launch_bounds__(256)
k_wsplit_all(const float* __restrict__ gcnW, const float* __restrict__ Wih,
             const float* __restrict__ Whh, const float* __restrict__ fc1W,
             const float* __restrict__ dh1W, const float* __restrict__ fc2W,
             const float* __restrict__ fc1b, const float* __restrict__ dh1b) {
    const int task = blockIdx.y;
    const int tid0 = blockIdx.x * blockDim.x + threadIdx.x;
    const int stride = gridDim.x * blockDim.x;
    if (task < 3) {                 // gcnW layer: in [256(K),256(M)] -> out [M, 512] transposed
        const float* in = gcnW + (size_t)task * 256 * 256;
        __nv_bfloat16* out = g_gcnWs + (size_t)task * 256 * 512;
        for (int idx = tid0; idx < 256 * 256; idx += stride) {
            int k = idx >> 8, m = idx & 255;
            split_write(in[idx], &out[(long)m * 512 + k], &out[(long)m * 512 + 256 + k]);
        }
    } else if (task < 5) {          // Wih / Whh: [768, 256] row-major, float4 split
        const float* in = (task == 3) ? Wih : Whh;
        __nv_bfloat16* out = (task == 3) ? g_Wihs : g_Whhs;
        for (int idx = tid0; idx < 768 * 64; idx += stride) {
            long r = idx >> 6; int c = (idx & 63) << 2;
            float4 v = *reinterpret_cast<const float4*>(in + r * 256 + c);
            split_write4(v, &out[r * 512 + c], &out[r * 512 + 256 + c]);
        }
    } else if (task == 5) {         // fc1W [128,256] -> cWs rows 0..127
        for (int idx = tid0; idx < 128 * 64; idx += stride) {
            long r = idx >> 6; int c = (idx & 63) << 2;
            float4 v = *reinterpret_cast<const float4*>(fc1W + r * 256 + c);
            split_write4(v, &g_cWs[r * 512 + c], &g_cWs[r * 512 + 256 + c]);
        }
    } else if (task == 6) {         // dh1W [64,256] -> cWs rows 128..191
        __nv_bfloat16* out = g_cWs + (size_t)128 * 512;
        for (int idx = tid0; idx < 64 * 64; idx += stride) {
            long r = idx >> 6; int c = (idx & 63) << 2;
            float4 v = *reinterpret_cast<const float4*>(dh1W + r * 256 + c);
            split_write4(v, &out[r * 512 + c], &out[r * 512 + 256 + c]);
        }
    } else if (task == 7) {         // fc2W [64,128]
        for (int idx = tid0; idx < 64 * 32; idx += stride) {
            long r = idx >> 5; int c = (idx & 31) << 2;
            float4 v = *reinterpret_cast<const float4*>(fc2W + r * 128 + c);
            split_write4(v, &g_fc2Ws[r * 256 + c], &g_fc2Ws[r * 256 + 128 + c]);
        }
    } else {                        // bias concat fc1b|dh1b -> cb
        for (int idx = tid0; idx < 192; idx += stride)
            g_cb[idx] = (idx < 128) ? fc1b[idx] : dh1b[idx - 128];
    }
}

// ---- bf16 mma.sync GEMM: proven core (128x128, 256 thr, 2 CTA/SM) ----
#define SROW2 40
#define ARR_B (128 * SROW2 * 2)
#define STAGE_B (4 * ARR_B)
#define GEMM_SMEM (2 * STAGE_B)
template <int ACT, int MODE>
__global__ void __launch_bounds__(256, 2)
gemm_mma(const __nv_bfloat16* __restrict__ A, const __nv_bfloat16* __restrict__ B,
         const float* __restrict__ bias, float* __restrict__ outF,
         __nv_bfloat16* __restrict__ outS, int R, int M, int K) {
    extern __shared__ __align__(16) __nv_bfloat16 smg[];
    const uint32_t sbase = (uint32_t)__cvta_generic_to_shared(smg);

    const int tid  = threadIdx.x;
    const int lane = tid & 31, wid = tid >> 5;
    const int wm = wid & 1;
    const int wn = wid >> 1;
    const long rowA = (long)blockIdx.y * 128;
    const long colB = (long)blockIdx.x * 128;
    const int K2 = 2 * K;
    const int NC = K >> 5;

    const int arrid = tid >> 6;
    const int l6    = tid & 63;
    const int row0  = (l6 >> 2) * 8;
    const int seg   = l6 & 3;
    const bool isA  = arrid < 2;
    const long rb   = (isA ? rowA : colB) + row0;
    const int  lim  = isA ? R : M;
    int szs[8];
#pragma unroll
    for (int u = 0; u < 8; u++) szs[u] = (rb + u < lim) ? 16 : 0;
    const __nv_bfloat16* sp = (isA ? A : B) + rb * (long)K2 +
                              ((arrid & 1) ? K : 0) + seg * 8;
    const uint32_t dstb = (uint32_t)arrid * ARR_B +
                          (uint32_t)(row0 * SROW2 + seg * 8) * 2;

    float acc[4][4][4];
#pragma unroll
    for (int i = 0; i < 4; i++)
#pragma unroll
        for (int j = 0; j < 4; j++)
#pragma unroll
            for (int k = 0; k < 4; k++) acc[i][j][k] = 0.0f;

    auto ld_chunk = [&](int c, int buf) {
        uint32_t stg = sbase + (uint32_t)buf * STAGE_B + dstb;
        const __nv_bfloat16* s = sp + (long)c * 32;
#pragma unroll
        for (int u = 0; u < 8; u++)
            cpa16z(stg + (uint32_t)(u * SROW2 * 2), s + (long)u * K2, szs[u]);
        asm volatile("cp.async.commit_group;" ::: "memory");
    };

    ld_chunk(0, 0);

    const uint32_t aOffC = ((uint32_t)(wm * 64 + (lane & 15)) * SROW2 + (lane >> 4) * 8) * 2;
    const uint32_t bOffC = ((uint32_t)(wn * 32 + ((lane >> 4) & 1) * 8 + (lane & 7)) * SROW2 +
                            ((lane >> 3) & 1) * 8) * 2;

    for (int c = 0; c < NC; c++) {
        int buf = c & 1;
        if (c + 1 < NC) {
            ld_chunk(c + 1, buf ^ 1);
            asm volatile("cp.async.wait_group 1;" ::: "memory");
        } else {
            asm volatile("cp.async.wait_group 0;" ::: "memory");
        }
        __syncthreads();
        uint32_t stg = sbase + (uint32_t)buf * STAGE_B;
        uint32_t ah = stg + aOffC;
        uint32_t al = ah + ARR_B;
        uint32_t bh = stg + 2 * ARR_B + bOffC;
        uint32_t bl = bh + ARR_B;
#pragma unroll
        for (int ks = 0; ks < 2; ks++) {
            uint32_t koff = (uint32_t)(ks * 16) * 2;
            uint32_t bhf[2][4], blf[2][4];
#pragma unroll
            for (int nt = 0; nt < 2; nt++) {
                ldsm4(bhf[nt], bh + (uint32_t)(nt * 16 * SROW2) * 2 + koff);
                ldsm4(blf[nt], bl + (uint32_t)(nt * 16 * SROW2) * 2 + koff);
            }
#pragma unroll
            for (int half = 0; half < 2; half++) {
                uint32_t ahf[2][4], alf[2][4];
#pragma unroll
                for (int m2 = 0; m2 < 2; m2++) {
                    int mt = half * 2 + m2;
                    ldsm4(ahf[m2], ah + (uint32_t)(mt * 16 * SROW2) * 2 + koff);
                    ldsm4(alf[m2], al + (uint32_t)(mt * 16 * SROW2) * 2 + koff);
                }
#pragma unroll
                for (int m2 = 0; m2 < 2; m2++)
#pragma unroll
                    for (int j = 0; j < 4; j++)
                        mma16816(acc[half * 2 + m2][j], ahf[m2], &bhf[j >> 1][(j & 1) * 2]);
#pragma unroll
                for (int m2 = 0; m2 < 2; m2++)
#pragma unroll
                    for (int j = 0; j < 4; j++)
                        mma16816(acc[half * 2 + m2][j], ahf[m2], &blf[j >> 1][(j & 1) * 2]);
#pragma unroll
                for (int m2 = 0; m2 < 2; m2++)
#pragma unroll
                    for (int j = 0; j < 4; j++)
                        mma16816(acc[half * 2 + m2][j], alf[m2], &bhf[j >> 1][(j & 1) * 2]);
            }
        }
        __syncthreads();
    }

    // vectorized epilogue
#pragma unroll
    for (int mt = 0; mt < 4; mt++) {
        long r0e = rowA + wm * 64 + mt * 16 + (lane >> 2);
#pragma unroll
        for (int j = 0; j < 4; j++) {
            int col0 = (int)colB + wn * 32 + j * 8 + (lane & 3) * 2;
            if (col0 >= M) continue;
            float2 b2 = make_float2(0.f, 0.f);
            if (bias) b2 = *reinterpret_cast<const float2*>(bias + col0);
#pragma unroll
            for (int half = 0; half < 2; half++) {
                long r = r0e + half * 8;
                if (r >= R) continue;
                float v0 = acc[mt][j][half * 2 + 0] + b2.x;
                float v1 = acc[mt][j][half * 2 + 1] + b2.y;
                if (ACT) { v0 = gelu1(v0); v1 = gelu1(v1); }
                if (MODE == 0) {
                    *reinterpret_cast<float2*>(outF + r * (long)M + col0) = make_float2(v0, v1);
                } else {   // MODE 3: fused fc1|dh1
                    if (col0 < 128)
                        split_write2(v0, v1, &outS[r * 256 + col0], &outS[r * 256 + 128 + col0]);
                    else
                        *reinterpret_cast<float2*>(outF + r * 64 + (col0 - 128)) =
                            make_float2(v0, v1);
                }
            }
        }
    }
}

// ---- GCN aggregate, 4 snapshots x 64-thread groups, float4 gathers, unroll-4 ----
__global__ void __launch_bounds__(256)
k_gcn_agg4(const float* __restrict__ hW,
           const float* __restrict__ bias, const float* __restrict__ g,
           const float* __restrict__ b, __nv_bfloat16* __restrict__ out) {
    const int t  = blockIdx.x;
    const int si = threadIdx.x >> 6;
    const int l6 = threadIdx.x & 63;
    const int d4 = l6 << 2;
    const float di = g_dinv[t];
    const float di2 = di * di;
    const float* base = hW + (size_t)si * Nn * Dd;

    float4 acc = *reinterpret_cast<const float4*>(base + (size_t)t * Dd + d4);
    acc.x *= di2; acc.y *= di2; acc.z *= di2; acc.w *= di2;

    const int e0 = g_rowp[t], e1 = g_rowp[t + 1];
    int e = e0;
    const int eb = e0 + ((e1 - e0) & ~3);
    for (; e < eb; e += 4) {
        int s0 = __ldg(&g_csrc[e]);
        int s1 = __ldg(&g_csrc[e + 1]);
        int s2 = __ldg(&g_csrc[e + 2]);
        int s3 = __ldg(&g_csrc[e + 3]);
        float n0 = __ldg(&g_cnorm[e]);
        float n1 = __ldg(&g_cnorm[e + 1]);
        float n2 = __ldg(&g_cnorm[e + 2]);
        float n3 = __ldg(&g_cnorm[e + 3]);
        float4 v0 = *reinterpret_cast<const float4*>(base + (size_t)s0 * Dd + d4);
        float4 v1 = *reinterpret_cast<const float4*>(base + (size_t)s1 * Dd + d4);
        float4 v2 = *reinterpret_cast<const float4*>(base + (size_t)s2 * Dd + d4);
        float4 v3 = *reinterpret_cast<const float4*>(base + (size_t)s3 * Dd + d4);
        acc.x += n0 * v0.x + n1 * v1.x + n2 * v2.x + n3 * v3.x;
        acc.y += n0 * v0.y + n1 * v1.y + n2 * v2.y + n3 * v3.y;
        acc.z += n0 * v0.z + n1 * v1.z + n2 * v2.z + n3 * v3.z;
        acc.w += n0 * v0.w + n1 * v1.w + n2 * v2.w + n3 * v3.w;
    }
    for (; e < e1; e++) {
        int s = __ldg(&g_csrc[e]);
        float nm = __ldg(&g_cnorm[e]);
        float4 v = *reinterpret_cast<const float4*>(base + (size_t)s * Dd + d4);
        acc.x += nm * v.x; acc.y += nm * v.y; acc.z += nm * v.z; acc.w += nm * v.w;
    }
    float4 bb = *reinterpret_cast<const float4*>(bias + d4);
    acc.x += bb.x; acc.y += bb.y; acc.z += bb.z; acc.w += bb.w;

    __shared__ float rs[8], rq[8];
    __shared__ float mvm[Ss], mvr[Ss];
    float sum = acc.x + acc.y + acc.z + acc.w;
    float sq  = acc.x * acc.x + acc.y * acc.y + acc.z * acc.z + acc.w * acc.w;
    const int lane = threadIdx.x & 31, wd = threadIdx.x >> 5;
#pragma unroll
    for (int o = 16; o; o >>= 1) {
        sum += __shfl_down_sync(0xffffffffu, sum, o);
        sq  += __shfl_down_sync(0xffffffffu, sq, o);
    }
    if (lane == 0) { rs[wd] = sum; rq[wd] = sq; }
    __syncthreads();
    if (threadIdx.x < Ss) {
        float ss = rs[2 * threadIdx.x] + rs[2 * threadIdx.x + 1];
        float qq = rq[2 * threadIdx.x] + rq[2 * threadIdx.x + 1];
        float m = ss * (1.0f / 256.0f);
        float var = qq * (1.0f / 256.0f) - m * m;
        mvm[threadIdx.x] = m;
        mvr[threadIdx.x] = rsqrtf(var + 1e-5f);
    }
    __syncthreads();
    const float m = mvm[si], rstd = mvr[si];
    float4 gg = *reinterpret_cast<const float4*>(g + d4);
    float4 b2 = *reinterpret_cast<const float4*>(b + d4);
    float4 val;
    val.x = fmaxf((acc.x - m) * rstd * gg.x + b2.x, 0.0f);
    val.y = fmaxf((acc.y - m) * rstd * gg.y + b2.y, 0.0f);
    val.z = fmaxf((acc.z - m) * rstd * gg.z + b2.z, 0.0f);
    val.w = fmaxf((acc.w - m) * rstd * gg.w + b2.w, 0.0f);
    __nv_bfloat16* o = out + ((size_t)si * Nn + t) * 512;
    split_write4(val, &o[d4], &o[256 + d4]);
}

// ---------------- GRU cell, float4 vectorized ----------------
__global__ void k_gru_cell(const float* __restrict__ gi, const float* __restrict__ gh,
                           const float* __restrict__ bhh, const float* __restrict__ hprev,
                           float* __restrict__ hnew, __nv_bfloat16* __restrict__ hs,
                           int first) {
    int idx = blockIdx.x * blockDim.x + threadIdx.x;
    if (idx >= Nn * 64) return;
    int n = idx >> 6, d = (idx & 63) << 2;
    const float* gir = gi + (size_t)n * 768;
    float4 ir = *reinterpret_cast<const float4*>(gir + d);
    float4 iz = *reinterpret_cast<const float4*>(gir + 256 + d);
    float4 ig = *reinterpret_cast<const float4*>(gir + 512 + d);
    float4 hr, hz, hg, hp;
    if (first) {
        hr = *reinterpret_cast<const float4*>(bhh + d);
        hz = *reinterpret_cast<const float4*>(bhh + 256 + d);
        hg = *reinterpret_cast<const float4*>(bhh + 512 + d);
        hp = make_float4(0.f, 0.f, 0.f, 0.f);
    } else {
        const float* ghr = gh + (size_t)n * 768;
        hr = *reinterpret_cast<const float4*>(ghr + d);
        hz = *reinterpret_cast<const float4*>(ghr + 256 + d);
        hg = *reinterpret_cast<const float4*>(ghr + 512 + d);
        hp = *reinterpret_cast<const float4*>(hprev + (size_t)n * 256 + d);
    }
    float4 v;
#define GRU1(c) { \
        float r = 1.0f / (1.0f + expf(-(ir.c + hr.c))); \
        float z = 1.0f / (1.0f + expf(-(iz.c + hz.c))); \
        float ng = tanhf(ig.c + r * hg.c); \
        v.c = (1.0f - z) * ng + z * hp.c; }
    GRU1(x) GRU1(y) GRU1(z) GRU1(w)
#undef GRU1
    *reinterpret_cast<float4*>(hnew + (size_t)n * 256 + d) = v;
    split_write4(v, &hs[(size_t)n * 512 + d], &hs[(size_t)n * 512 + 256 + d]);
}

// ---------------- both head GEMMs in one launch (blockIdx.y selects) ----------------
__global__ void __launch_bounds__(256)
k_head5x2(const float* __restrict__ inF, const float* __restrict__ WF,
          const float* __restrict__ bF, float* __restrict__ outFc,
          const float* __restrict__ inD, const float* __restrict__ WD,
          const float* __restrict__ bD, float* __restrict__ outDc) {
    const float* in   = blockIdx.y ? inD : inF;
    const float* W    = blockIdx.y ? WD : WF;
    const float* bias = blockIdx.y ? bD : bF;
    float* out        = blockIdx.y ? outDc : outFc;
    __shared__ float sW[5 * 64];
    for (int i = threadIdx.x; i < 5 * 64; i += blockDim.x) sW[i] = W[i];
    __syncthreads();
    int gw = (blockIdx.x * blockDim.x + threadIdx.x) >> 5;
    int lane = threadIdx.x & 31;
    if (gw >= Nn) return;
    float x0 = in[(size_t)gw * 64 + lane];
    float x1 = in[(size_t)gw * 64 + 32 + lane];
#pragma unroll
    for (int m = 0; m < 5; m++) {
        float p = x0 * sW[m * 64 + lane] + x1 * sW[m * 64 + 32 + lane];
#pragma unroll
        for (int o = 16; o; o >>= 1) p += __shfl_down_sync(0xffffffffu, p, o);
        if (lane == 0) out[(size_t)gw * 5 + m] = p + bias[m];
    }
}

// ---------------- host orchestration ----------------
template <typename T>
static T* symp(const void* sym) {
    void* p = nullptr;
    cudaGetSymbolAddress(&p, sym);
    return (T*)p;
}

extern "C" void kernel_launch(void* const* d_in, const int* in_sizes, int n_in,
                              void* d_out, int out_size) {
    const float* x    = (const float*)d_in[0];
    const int*   esrc = (const int*)d_in[1];
    const int*   edst = (const int*)d_in[2];
    const float* ew   = (const float*)d_in[3];
    const float* gcnW = (const float*)d_in[4];
    const float* gcnb = (const float*)d_in[5];
    const float* lng  = (const float*)d_in[6];
    const float* lnb  = (const float*)d_in[7];
    const float* Wih  = (const float*)d_in[8];
    const float* Whh  = (const float*)d_in[9];
    const float* bih  = (const float*)d_in[10];
    const float* bhh  = (const float*)d_in[11];
    const float* fc1W = (const float*)d_in[12];
    const float* fc1b = (const float*)d_in[13];
    const float* fc2W = (const float*)d_in[14];
    const float* fc2b = (const float*)d_in[15];
    const float* fc3W = (const float*)d_in[16];
    const float* fc3b = (const float*)d_in[17];
    const float* dh1W = (const float*)d_in[18];
    const float* dh1b = (const float*)d_in[19];
    const float* dh2W = (const float*)d_in[20];
    const float* dh2b = (const float*)d_in[21];

    float* outF = (float*)d_out;
    float* outD = outF + (size_t)Nn * Hh;

    float* tmpW  = symp<float>(g_tmpW);
    float* giAll = symp<float>(g_giAll);
    float* gh    = symp<float>(g_gh);
    float* h1    = symp<float>(g_h1);
    float* h2    = symp<float>(g_h2);
    float* f2    = symp<float>(g_f2);
    float* d1    = symp<float>(g_d1);
    float* cb    = symp<float>(g_cb);
    __nv_bfloat16* xs    = symp<__nv_bfloat16>(g_xs);
    __nv_bfloat16* aggA  = symp<__nv_bfloat16>(g_aggA);
    __nv_bfloat16* seqs  = symp<__nv_bfloat16>(g_seqs);
    __nv_bfloat16* hs    = symp<__nv_bfloat16>(g_hs);
    __nv_bfloat16* f1s   = symp<__nv_bfloat16>(g_f1s);
    __nv_bfloat16* gcnWs = symp<__nv_bfloat16>(g_gcnWs);
    __nv_bfloat16* Wihs  = symp<__nv_bfloat16>(g_Wihs);
    __nv_bfloat16* Whhs  = symp<__nv_bfloat16>(g_Whhs);
    __nv_bfloat16* cWs   = symp<__nv_bfloat16>(g_cWs);
    __nv_bfloat16* fc2Ws = symp<__nv_bfloat16>(g_fc2Ws);

    cudaFuncSetAttribute(gemm_mma<0, 0>, cudaFuncAttributeMaxDynamicSharedMemorySize, GEMM_SMEM);
    cudaFuncSetAttribute(gemm_mma<0, 0>, cudaFuncAttributePreferredSharedMemoryCarveout, 100);
    cudaFuncSetAttribute(gemm_mma<1, 0>, cudaFuncAttributeMaxDynamicSharedMemorySize, GEMM_SMEM);
    cudaFuncSetAttribute(gemm_mma<1, 0>, cudaFuncAttributePreferredSharedMemoryCarveout, 100);
    cudaFuncSetAttribute(gemm_mma<1, 3>, cudaFuncAttributeMaxDynamicSharedMemorySize, GEMM_SMEM);
    cudaFuncSetAttribute(gemm_mma<1, 3>, cudaFuncAttributePreferredSharedMemoryCarveout, 100);

    const int TB = 256;
    const int gN = (Nn + TB - 1) / TB;
    const int gE = (Ee + TB - 1) / TB;

    dim3 blk(256);
    const int RB4 = (SN + 127) / 128;   // 625
    const int RB1 = (Nn + 127) / 128;   // 157
    dim3 gGCN(2, RB4);
    dim3 gGI(6, RB4);
    dim3 gGRU(6, RB1);
    dim3 gHC(2, RB1);
    dim3 gH1(1, RB1);

    // ---- prologue: big GCN GEMM stays at launch slot #4 (ncu -s 5) ----
    k_wsplit_all<<<dim3(64, 9), TB>>>(gcnW, Wih, Whh, fc1W, dh1W, fc2W, fc1b, dh1b);    // #1
    k_split<<<((long)SN * 64 + TB - 1) / TB, TB>>>(x, xs, (long)SN * 64, 64);           // #2
    k_init_deg_cnt<<<gN, TB>>>();                                                       // #3
    gemm_mma<0, 0><<<gGCN, blk, GEMM_SMEM>>>(xs, gcnWs, nullptr, tmpW, nullptr,
                                             SN, 256, 256);                             // #4 <- profile
    // graph preprocessing -> CSR
    k_edge_deg_cnt<<<gE, TB>>>(edst, ew);
    k_scan1<<<NB, 256>>>();          // dinv fused
    k_scan2<<<1, 128>>>();
    k_scan3<<<NB, 256>>>();
    k_fill_csr<<<gE, TB>>>(esrc, edst, ew);

    // batched GCN stack: aggregation fuses ALL 4 snapshots per block
    k_gcn_agg4<<<Nn, 256>>>(tmpW, gcnb + 0 * Dd, lng + 0 * Dd, lnb + 0 * Dd, aggA);
    gemm_mma<0, 0><<<gGCN, blk, GEMM_SMEM>>>(aggA, gcnWs + 1 * 256 * 512, nullptr, tmpW,
                                             nullptr, SN, 256, 256);
    k_gcn_agg4<<<Nn, 256>>>(tmpW, gcnb + 1 * Dd, lng + 1 * Dd, lnb + 1 * Dd, aggA);
    gemm_mma<0, 0><<<gGCN, blk, GEMM_SMEM>>>(aggA, gcnWs + 2 * 256 * 512, nullptr, tmpW,
                                             nullptr, SN, 256, 256);
    k_gcn_agg4<<<Nn, 256>>>(tmpW, gcnb + 2 * Dd, lng + 2 * Dd, lnb + 2 * Dd, seqs);

    // gi for ALL timesteps in one GEMM
    gemm_mma<0, 0><<<gGI, blk, GEMM_SMEM>>>(seqs, Wihs, bih, giAll, nullptr, SN, 768, 256);

    // GRU recurrence
    const int gCell = (Nn * 64 + TB - 1) / TB;
    k_gru_cell<<<gCell, TB>>>(giAll, gh, bhh, h1, h1, hs, 1);
    for (int t = 1; t < Ss; t++) {
        float* hp = (t & 1) ? h1 : h2;
        float* hn = (t & 1) ? h2 : h1;
        gemm_mma<0, 0><<<gGRU, blk, GEMM_SMEM>>>(hs, Whhs, bhh, gh, nullptr, Nn, 768, 256);
        k_gru_cell<<<gCell, TB>>>(giAll + (size_t)t * Nn * 768, gh, bhh, hp, hn, hs, 0);
    }

    // fused fc1|dh1 GEMM (M=192), fc2, then both tiny heads in ONE launch
    gemm_mma<1, 3><<<gHC, blk, GEMM_SMEM>>>(hs, cWs, cb, d1, f1s, Nn, 192, 256);
    gemm_mma<1, 0><<<gH1, blk, GEMM_SMEM>>>(f1s, fc2Ws, fc2b, f2, nullptr, Nn, 64, 128);
    k_head5x2<<<dim3((Nn * 32 + TB - 1) / TB, 2), TB>>>(f2, fc3W, fc3b, outF,
                                                        d1, dh2W, dh2b, outD);
}

// round 17
// speedup vs baseline: 1.1639x; 1.0089x over previous
#include <cuda_runtime.h>
#include <cuda_bf16.h>
#include <math.h>
#include <stdint.h>

#define Nn 20000
#define Dd 256
#define Ss 4
#define Ee 320000
#define Hh 5
#define SN (Ss * Nn)
#define NB 79                      // ceil(Nn/256)

// ---------------- scratch (device globals; no allocs allowed) ----------------
__device__ float g_deg[Nn];
__device__ float g_dinv[Nn];
__device__ int   g_cnt[Nn];
__device__ int   g_rowp[Nn + 1];
__device__ int   g_fill[Nn];
__device__ int   g_bsum[NB + 1];
__device__ int   g_boff[NB + 1];
__device__ int   g_csrc[Ee];
__device__ float g_cnorm[Ee];

__device__ float g_tmpW[SN * Dd];
__device__ float g_giAll[SN * 3 * Dd];
__device__ float g_gh[Nn * 3 * Dd];
__device__ float g_h1[Nn * Dd];
__device__ float g_h2[Nn * Dd];
__device__ float g_f2[Nn * 64];
__device__ float g_d1[Nn * 64];
__device__ float g_cb[192];

// split-bf16 activations: layout [rows, 2K] = [hi | lo]
__device__ __nv_bfloat16 g_xs[SN * 512];
__device__ __nv_bfloat16 g_aggA[SN * 512];
__device__ __nv_bfloat16 g_seqs[SN * 512];
__device__ __nv_bfloat16 g_hs[Nn * 512];
__device__ __nv_bfloat16 g_f1s[Nn * 256];

// split-bf16 weights: [M, 2K]
__device__ __nv_bfloat16 g_gcnWs[3 * 256 * 512];
__device__ __nv_bfloat16 g_Wihs[768 * 512];
__device__ __nv_bfloat16 g_Whhs[768 * 512];
__device__ __nv_bfloat16 g_cWs[192 * 512];
__device__ __nv_bfloat16 g_fc2Ws[64 * 256];

// ---------------- helpers ----------------
__device__ __forceinline__ void split_write(float v, __nv_bfloat16* hi, __nv_bfloat16* lo) {
    __nv_bfloat16 h = __float2bfloat16(v);
    *hi = h;
    *lo = __float2bfloat16(v - __bfloat162float(h));
}
__device__ __forceinline__ void split_write2(float v0, float v1,
                                             __nv_bfloat16* hi, __nv_bfloat16* lo) {
    __nv_bfloat16 h0 = __float2bfloat16(v0), h1 = __float2bfloat16(v1);
    __nv_bfloat162 hh; hh.x = h0; hh.y = h1;
    *reinterpret_cast<__nv_bfloat162*>(hi) = hh;
    __nv_bfloat162 ll;
    ll.x = __float2bfloat16(v0 - __bfloat162float(h0));
    ll.y = __float2bfloat16(v1 - __bfloat162float(h1));
    *reinterpret_cast<__nv_bfloat162*>(lo) = ll;
}
__device__ __forceinline__ void split_write4(float4 v, __nv_bfloat16* hi, __nv_bfloat16* lo) {
    split_write2(v.x, v.y, hi, lo);
    split_write2(v.z, v.w, hi + 2, lo + 2);
}
__device__ __forceinline__ void ldsm4(uint32_t* r, uint32_t addr) {
    asm volatile("ldmatrix.sync.aligned.m8n8.x4.shared.b16 {%0,%1,%2,%3}, [%4];"
                 : "=r"(r[0]), "=r"(r[1]), "=r"(r[2]), "=r"(r[3]) : "r"(addr));
}
__device__ __forceinline__ void mma16816(float* c, const uint32_t* a, const uint32_t* b) {
    asm volatile(
        "mma.sync.aligned.m16n8k16.row.col.f32.bf16.bf16.f32 "
        "{%0,%1,%2,%3}, {%4,%5,%6,%7}, {%8,%9}, {%0,%1,%2,%3};"
        : "+f"(c[0]), "+f"(c[1]), "+f"(c[2]), "+f"(c[3])
        : "r"(a[0]), "r"(a[1]), "r"(a[2]), "r"(a[3]), "r"(b[0]), "r"(b[1]));
}
__device__ __forceinline__ void cpa16z(uint32_t dst, const void* src, int sz) {
    asm volatile("cp.async.cg.shared.global [%0], [%1], 16, %2;"
                 :: "r"(dst), "l"(src), "r"(sz));
}
__device__ __forceinline__ float gelu1(float v) {
    return 0.5f * v * (1.0f + erff(v * 0.7071067811865475f));
}

// ---------------- graph preprocessing ----------------
__global__ void k_init_deg_cnt() {
    int i = blockIdx.x * blockDim.x + threadIdx.x;
    if (i < Nn) { g_deg[i] = 1.0f; g_cnt[i] = 0; }
}
__global__ void k_edge_deg_cnt(const int* __restrict__ dst, const float* __restrict__ w) {
    int e = blockIdx.x * blockDim.x + threadIdx.x;
    if (e < Ee) {
        int t = dst[e];
        atomicAdd(&g_deg[t], w[e]);
        atomicAdd(&g_cnt[t], 1);
    }
}
__global__ void __launch_bounds__(256) k_scan1() {
    __shared__ int wsum[8];
    int i = blockIdx.x * 256 + threadIdx.x;
    int lane = threadIdx.x & 31, wd = threadIdx.x >> 5;
    if (i < Nn) g_dinv[i] = rsqrtf(g_deg[i]);
    int v = (i < Nn) ? g_cnt[i] : 0;
    int x = v;
#pragma unroll
    for (int o = 1; o < 32; o <<= 1) {
        int y = __shfl_up_sync(0xffffffffu, x, o);
        if (lane >= o) x += y;
    }
    if (lane == 31) wsum[wd] = x;
    __syncthreads();
    if (threadIdx.x == 0) {
        int acc = 0;
#pragma unroll
        for (int w = 0; w < 8; w++) { int t = wsum[w]; wsum[w] = acc; acc += t; }
        g_bsum[blockIdx.x] = acc;
    }
    __syncthreads();
    if (i < Nn) g_rowp[i] = wsum[wd] + x - v;
}
__global__ void k_scan2() {
    int t = threadIdx.x;
    __shared__ int sh[NB];
    if (t < NB) sh[t] = g_bsum[t];
    __syncthreads();
    if (t == 0) {
        int acc = 0;
        for (int b = 0; b < NB; b++) { int v = sh[b]; g_boff[b] = acc; acc += v; }
        g_rowp[Nn] = acc;
    }
}
__global__ void __launch_bounds__(256) k_scan3() {
    int i = blockIdx.x * 256 + threadIdx.x;
    if (i < Nn) {
        int r = g_rowp[i] + g_boff[blockIdx.x];
        g_rowp[i] = r;
        g_fill[i] = r;
    }
}
__global__ void k_fill_csr(const int* __restrict__ src, const int* __restrict__ dst,
                           const float* __restrict__ w) {
    int e = blockIdx.x * blockDim.x + threadIdx.x;
    if (e < Ee) {
        int s = src[e], t = dst[e];
        int pos = atomicAdd(&g_fill[t], 1);
        g_csrc[pos]  = s;
        g_cnorm[pos] = g_dinv[s] * w[e] * g_dinv[t];
    }
}

// ---------------- split conversion ----------------
__global__ void k_split(const float* __restrict__ in, __nv_bfloat16* __restrict__ out,
                        long total4, int K4) {
    long idx = (long)blockIdx.x * blockDim.x + threadIdx.x;
    if (idx >= total4) return;
    long r = idx / K4;
    int  c = (int)(idx - r * K4) * 4;
    int  K = K4 * 4;
    float4 v = *reinterpret_cast<const float4*>(in + r * K + c);
    split_write4(v, &out[r * 2 * K + c], &out[r * 2 * K + K + c]);
}
__global__ void __launch_bounds__(256)
k_wsplit_all(const float* __restrict__ gcnW, const float* __restrict__ Wih,
             const float* __restrict__ Whh, const float* __restrict__ fc1W,
             const float* __restrict__ dh1W, const float* __restrict__ fc2W,
             const float* __restrict__ fc1b, const float* __restrict__ dh1b) {
    const int task = blockIdx.y;
    const int tid0 = blockIdx.x * blockDim.x + threadIdx.x;
    const int stride = gridDim.x * blockDim.x;
    if (task < 3) {
        const float* in = gcnW + (size_t)task * 256 * 256;
        __nv_bfloat16* out = g_gcnWs + (size_t)task * 256 * 512;
        for (int idx = tid0; idx < 256 * 256; idx += stride) {
            int k = idx >> 8, m = idx & 255;
            split_write(in[idx], &out[(long)m * 512 + k], &out[(long)m * 512 + 256 + k]);
        }
    } else if (task < 5) {
        const float* in = (task == 3) ? Wih : Whh;
        __nv_bfloat16* out = (task == 3) ? g_Wihs : g_Whhs;
        for (int idx = tid0; idx < 768 * 64; idx += stride) {
            long r = idx >> 6; int c = (idx & 63) << 2;
            float4 v = *reinterpret_cast<const float4*>(in + r * 256 + c);
            split_write4(v, &out[r * 512 + c], &out[r * 512 + 256 + c]);
        }
    } else if (task == 5) {
        for (int idx = tid0; idx < 128 * 64; idx += stride) {
            long r = idx >> 6; int c = (idx & 63) << 2;
            float4 v = *reinterpret_cast<const float4*>(fc1W + r * 256 + c);
            split_write4(v, &g_cWs[r * 512 + c], &g_cWs[r * 512 + 256 + c]);
        }
    } else if (task == 6) {
        __nv_bfloat16* out = g_cWs + (size_t)128 * 512;
        for (int idx = tid0; idx < 64 * 64; idx += stride) {
            long r = idx >> 6; int c = (idx & 63) << 2;
            float4 v = *reinterpret_cast<const float4*>(dh1W + r * 256 + c);
            split_write4(v, &out[r * 512 + c], &out[r * 512 + 256 + c]);
        }
    } else if (task == 7) {
        for (int idx = tid0; idx < 64 * 32; idx += stride) {
            long r = idx >> 5; int c = (idx & 31) << 2;
            float4 v = *reinterpret_cast<const float4*>(fc2W + r * 128 + c);
            split_write4(v, &g_fc2Ws[r * 256 + c], &g_fc2Ws[r * 256 + 128 + c]);
        }
    } else {
        for (int idx = tid0; idx < 192; idx += stride)
            g_cb[idx] = (idx < 128) ? fc1b[idx] : dh1b[idx - 128];
    }
}

// ---- bf16 mma.sync GEMM: proven core + SINGLE barrier per chunk ----
// Pipeline: wait_group 0 (chunk c arrived; committed one full iteration ago),
// __syncthreads (publishes chunk c AND certifies buf^1 reads from iter c-1 done),
// issue loads for c+1 into buf^1, compute chunk c from buf. One barrier/chunk.
#define SROW2 40
#define ARR_B (128 * SROW2 * 2)
#define STAGE_B (4 * ARR_B)
#define GEMM_SMEM (2 * STAGE_B)
template <int ACT, int MODE>
__global__ void __launch_bounds__(256, 2)
gemm_mma(const __nv_bfloat16* __restrict__ A, const __nv_bfloat16* __restrict__ B,
         const float* __restrict__ bias, float* __restrict__ outF,
         __nv_bfloat16* __restrict__ outS, int R, int M, int K) {
    extern __shared__ __align__(16) __nv_bfloat16 smg[];
    const uint32_t sbase = (uint32_t)__cvta_generic_to_shared(smg);

    const int tid  = threadIdx.x;
    const int lane = tid & 31, wid = tid >> 5;
    const int wm = wid & 1;
    const int wn = wid >> 1;
    const long rowA = (long)blockIdx.y * 128;
    const long colB = (long)blockIdx.x * 128;
    const int K2 = 2 * K;
    const int NC = K >> 5;

    const int arrid = tid >> 6;
    const int l6    = tid & 63;
    const int row0  = (l6 >> 2) * 8;
    const int seg   = l6 & 3;
    const bool isA  = arrid < 2;
    const long rb   = (isA ? rowA : colB) + row0;
    const int  lim  = isA ? R : M;
    int szs[8];
#pragma unroll
    for (int u = 0; u < 8; u++) szs[u] = (rb + u < lim) ? 16 : 0;
    const __nv_bfloat16* sp = (isA ? A : B) + rb * (long)K2 +
                              ((arrid & 1) ? K : 0) + seg * 8;
    const uint32_t dstb = (uint32_t)arrid * ARR_B +
                          (uint32_t)(row0 * SROW2 + seg * 8) * 2;

    float acc[4][4][4];
#pragma unroll
    for (int i = 0; i < 4; i++)
#pragma unroll
        for (int j = 0; j < 4; j++)
#pragma unroll
            for (int k = 0; k < 4; k++) acc[i][j][k] = 0.0f;

    auto ld_chunk = [&](int c, int buf) {
        uint32_t stg = sbase + (uint32_t)buf * STAGE_B + dstb;
        const __nv_bfloat16* s = sp + (long)c * 32;
#pragma unroll
        for (int u = 0; u < 8; u++)
            cpa16z(stg + (uint32_t)(u * SROW2 * 2), s + (long)u * K2, szs[u]);
        asm volatile("cp.async.commit_group;" ::: "memory");
    };

    ld_chunk(0, 0);

    const uint32_t aOffC = ((uint32_t)(wm * 64 + (lane & 15)) * SROW2 + (lane >> 4) * 8) * 2;
    const uint32_t bOffC = ((uint32_t)(wn * 32 + ((lane >> 4) & 1) * 8 + (lane & 7)) * SROW2 +
                            ((lane >> 3) & 1) * 8) * 2;

    for (int c = 0; c < NC; c++) {
        int buf = c & 1;
        asm volatile("cp.async.wait_group 0;" ::: "memory");   // chunk c arrived
        __syncthreads();                                        // publish + recycle-safe
        if (c + 1 < NC) ld_chunk(c + 1, buf ^ 1);               // prefetch into recycled buf
        uint32_t stg = sbase + (uint32_t)buf * STAGE_B;
        uint32_t ah = stg + aOffC;
        uint32_t al = ah + ARR_B;
        uint32_t bh = stg + 2 * ARR_B + bOffC;
        uint32_t bl = bh + ARR_B;
#pragma unroll
        for (int ks = 0; ks < 2; ks++) {
            uint32_t koff = (uint32_t)(ks * 16) * 2;
            uint32_t bhf[2][4], blf[2][4];
#pragma unroll
            for (int nt = 0; nt < 2; nt++) {
                ldsm4(bhf[nt], bh + (uint32_t)(nt * 16 * SROW2) * 2 + koff);
                ldsm4(blf[nt], bl + (uint32_t)(nt * 16 * SROW2) * 2 + koff);
            }
#pragma unroll
            for (int half = 0; half < 2; half++) {
                uint32_t ahf[2][4], alf[2][4];
#pragma unroll
                for (int m2 = 0; m2 < 2; m2++) {
                    int mt = half * 2 + m2;
                    ldsm4(ahf[m2], ah + (uint32_t)(mt * 16 * SROW2) * 2 + koff);
                    ldsm4(alf[m2], al + (uint32_t)(mt * 16 * SROW2) * 2 + koff);
                }
#pragma unroll
                for (int m2 = 0; m2 < 2; m2++)
#pragma unroll
                    for (int j = 0; j < 4; j++)
                        mma16816(acc[half * 2 + m2][j], ahf[m2], &bhf[j >> 1][(j & 1) * 2]);
#pragma unroll
                for (int m2 = 0; m2 < 2; m2++)
#pragma unroll
                    for (int j = 0; j < 4; j++)
                        mma16816(acc[half * 2 + m2][j], ahf[m2], &blf[j >> 1][(j & 1) * 2]);
#pragma unroll
                for (int m2 = 0; m2 < 2; m2++)
#pragma unroll
                    for (int j = 0; j < 4; j++)
                        mma16816(acc[half * 2 + m2][j], alf[m2], &bhf[j >> 1][(j & 1) * 2]);
            }
        }
    }

    // vectorized epilogue
#pragma unroll
    for (int mt = 0; mt < 4; mt++) {
        long r0e = rowA + wm * 64 + mt * 16 + (lane >> 2);
#pragma unroll
        for (int j = 0; j < 4; j++) {
            int col0 = (int)colB + wn * 32 + j * 8 + (lane & 3) * 2;
            if (col0 >= M) continue;
            float2 b2 = make_float2(0.f, 0.f);
            if (bias) b2 = *reinterpret_cast<const float2*>(bias + col0);
#pragma unroll
            for (int half = 0; half < 2; half++) {
                long r = r0e + half * 8;
                if (r >= R) continue;
                float v0 = acc[mt][j][half * 2 + 0] + b2.x;
                float v1 = acc[mt][j][half * 2 + 1] + b2.y;
                if (ACT) { v0 = gelu1(v0); v1 = gelu1(v1); }
                if (MODE == 0) {
                    *reinterpret_cast<float2*>(outF + r * (long)M + col0) = make_float2(v0, v1);
                } else {   // MODE 3: fused fc1|dh1
                    if (col0 < 128)
                        split_write2(v0, v1, &outS[r * 256 + col0], &outS[r * 256 + 128 + col0]);
                    else
                        *reinterpret_cast<float2*>(outF + r * 64 + (col0 - 128)) =
                            make_float2(v0, v1);
                }
            }
        }
    }
}

// ---- GCN aggregate, 4 snapshots x 64-thread groups, float4 gathers, unroll-4 ----
__global__ void __launch_bounds__(256)
k_gcn_agg4(const float* __restrict__ hW,
           const float* __restrict__ bias, const float* __restrict__ g,
           const float* __restrict__ b, __nv_bfloat16* __restrict__ out) {
    const int t  = blockIdx.x;
    const int si = threadIdx.x >> 6;
    const int l6 = threadIdx.x & 63;
    const int d4 = l6 << 2;
    const float di = g_dinv[t];
    const float di2 = di * di;
    const float* base = hW + (size_t)si * Nn * Dd;

    float4 acc = *reinterpret_cast<const float4*>(base + (size_t)t * Dd + d4);
    acc.x *= di2; acc.y *= di2; acc.z *= di2; acc.w *= di2;

    const int e0 = g_rowp[t], e1 = g_rowp[t + 1];
    int e = e0;
    const int eb = e0 + ((e1 - e0) & ~3);
    for (; e < eb; e += 4) {
        int s0 = __ldg(&g_csrc[e]);
        int s1 = __ldg(&g_csrc[e + 1]);
        int s2 = __ldg(&g_csrc[e + 2]);
        int s3 = __ldg(&g_csrc[e + 3]);
        float n0 = __ldg(&g_cnorm[e]);
        float n1 = __ldg(&g_cnorm[e + 1]);
        float n2 = __ldg(&g_cnorm[e + 2]);
        float n3 = __ldg(&g_cnorm[e + 3]);
        float4 v0 = *reinterpret_cast<const float4*>(base + (size_t)s0 * Dd + d4);
        float4 v1 = *reinterpret_cast<const float4*>(base + (size_t)s1 * Dd + d4);
        float4 v2 = *reinterpret_cast<const float4*>(base + (size_t)s2 * Dd + d4);
        float4 v3 = *reinterpret_cast<const float4*>(base + (size_t)s3 * Dd + d4);
        acc.x += n0 * v0.x + n1 * v1.x + n2 * v2.x + n3 * v3.x;
        acc.y += n0 * v0.y + n1 * v1.y + n2 * v2.y + n3 * v3.y;
        acc.z += n0 * v0.z + n1 * v1.z + n2 * v2.z + n3 * v3.z;
        acc.w += n0 * v0.w + n1 * v1.w + n2 * v2.w + n3 * v3.w;
    }
    for (; e < e1; e++) {
        int s = __ldg(&g_csrc[e]);
        float nm = __ldg(&g_cnorm[e]);
        float4 v = *reinterpret_cast<const float4*>(base + (size_t)s * Dd + d4);
        acc.x += nm * v.x; acc.y += nm * v.y; acc.z += nm * v.z; acc.w += nm * v.w;
    }
    float4 bb = *reinterpret_cast<const float4*>(bias + d4);
    acc.x += bb.x; acc.y += bb.y; acc.z += bb.z; acc.w += bb.w;

    __shared__ float rs[8], rq[8];
    __shared__ float mvm[Ss], mvr[Ss];
    float sum = acc.x + acc.y + acc.z + acc.w;
    float sq  = acc.x * acc.x + acc.y * acc.y + acc.z * acc.z + acc.w * acc.w;
    const int lane = threadIdx.x & 31, wd = threadIdx.x >> 5;
#pragma unroll
    for (int o = 16; o; o >>= 1) {
        sum += __shfl_down_sync(0xffffffffu, sum, o);
        sq  += __shfl_down_sync(0xffffffffu, sq, o);
    }
    if (lane == 0) { rs[wd] = sum; rq[wd] = sq; }
    __syncthreads();
    if (threadIdx.x < Ss) {
        float ss = rs[2 * threadIdx.x] + rs[2 * threadIdx.x + 1];
        float qq = rq[2 * threadIdx.x] + rq[2 * threadIdx.x + 1];
        float m = ss * (1.0f / 256.0f);
        float var = qq * (1.0f / 256.0f) - m * m;
        mvm[threadIdx.x] = m;
        mvr[threadIdx.x] = rsqrtf(var + 1e-5f);
    }
    __syncthreads();
    const float m = mvm[si], rstd = mvr[si];
    float4 gg = *reinterpret_cast<const float4*>(g + d4);
    float4 b2 = *reinterpret_cast<const float4*>(b + d4);
    float4 val;
    val.x = fmaxf((acc.x - m) * rstd * gg.x + b2.x, 0.0f);
    val.y = fmaxf((acc.y - m) * rstd * gg.y + b2.y, 0.0f);
    val.z = fmaxf((acc.z - m) * rstd * gg.z + b2.z, 0.0f);
    val.w = fmaxf((acc.w - m) * rstd * gg.w + b2.w, 0.0f);
    __nv_bfloat16* o = out + ((size_t)si * Nn + t) * 512;
    split_write4(val, &o[d4], &o[256 + d4]);
}

// ---------------- GRU cell, float4 vectorized ----------------
__global__ void k_gru_cell(const float* __restrict__ gi, const float* __restrict__ gh,
                           const float* __restrict__ bhh, const float* __restrict__ hprev,
                           float* __restrict__ hnew, __nv_bfloat16* __restrict__ hs,
                           int first) {
    int idx = blockIdx.x * blockDim.x + threadIdx.x;
    if (idx >= Nn * 64) return;
    int n = idx >> 6, d = (idx & 63) << 2;
    const float* gir = gi + (size_t)n * 768;
    float4 ir = *reinterpret_cast<const float4*>(gir + d);
    float4 iz = *reinterpret_cast<const float4*>(gir + 256 + d);
    float4 ig = *reinterpret_cast<const float4*>(gir + 512 + d);
    float4 hr, hz, hg, hp;
    if (first) {
        hr = *reinterpret_cast<const float4*>(bhh + d);
        hz = *reinterpret_cast<const float4*>(bhh + 256 + d);
        hg = *reinterpret_cast<const float4*>(bhh + 512 + d);
        hp = make_float4(0.f, 0.f, 0.f, 0.f);
    } else {
        const float* ghr = gh + (size_t)n * 768;
        hr = *reinterpret_cast<const float4*>(ghr + d);
        hz = *reinterpret_cast<const float4*>(ghr + 256 + d);
        hg = *reinterpret_cast<const float4*>(ghr + 512 + d);
        hp = *reinterpret_cast<const float4*>(hprev + (size_t)n * 256 + d);
    }
    float4 v;
#define GRU1(c) { \
        float r = 1.0f / (1.0f + expf(-(ir.c + hr.c))); \
        float z = 1.0f / (1.0f + expf(-(iz.c + hz.c))); \
        float ng = tanhf(ig.c + r * hg.c); \
        v.c = (1.0f - z) * ng + z * hp.c; }
    GRU1(x) GRU1(y) GRU1(z) GRU1(w)
#undef GRU1
    *reinterpret_cast<float4*>(hnew + (size_t)n * 256 + d) = v;
    split_write4(v, &hs[(size_t)n * 512 + d], &hs[(size_t)n * 512 + 256 + d]);
}

// ---------------- both head GEMMs in one launch ----------------
__global__ void __launch_bounds__(256)
k_head5x2(const float* __restrict__ inF, const float* __restrict__ WF,
          const float* __restrict__ bF, float* __restrict__ outFc,
          const float* __restrict__ inD, const float* __restrict__ WD,
          const float* __restrict__ bD, float* __restrict__ outDc) {
    const float* in   = blockIdx.y ? inD : inF;
    const float* W    = blockIdx.y ? WD : WF;
    const float* bias = blockIdx.y ? bD : bF;
    float* out        = blockIdx.y ? outDc : outFc;
    __shared__ float sW[5 * 64];
    for (int i = threadIdx.x; i < 5 * 64; i += blockDim.x) sW[i] = W[i];
    __syncthreads();
    int gw = (blockIdx.x * blockDim.x + threadIdx.x) >> 5;
    int lane = threadIdx.x & 31;
    if (gw >= Nn) return;
    float x0 = in[(size_t)gw * 64 + lane];
    float x1 = in[(size_t)gw * 64 + 32 + lane];
#pragma unroll
    for (int m = 0; m < 5; m++) {
        float p = x0 * sW[m * 64 + lane] + x1 * sW[m * 64 + 32 + lane];
#pragma unroll
        for (int o = 16; o; o >>= 1) p += __shfl_down_sync(0xffffffffu, p, o);
        if (lane == 0) out[(size_t)gw * 5 + m] = p + bias[m];
    }
}

// ---------------- host orchestration ----------------
template <typename T>
static T* symp(const void* sym) {
    void* p = nullptr;
    cudaGetSymbolAddress(&p, sym);
    return (T*)p;
}

extern "C" void kernel_launch(void* const* d_in, const int* in_sizes, int n_in,
                              void* d_out, int out_size) {
    const float* x    = (const float*)d_in[0];
    const int*   esrc = (const int*)d_in[1];
    const int*   edst = (const int*)d_in[2];
    const float* ew   = (const float*)d_in[3];
    const float* gcnW = (const float*)d_in[4];
    const float* gcnb = (const float*)d_in[5];
    const float* lng  = (const float*)d_in[6];
    const float* lnb  = (const float*)d_in[7];
    const float* Wih  = (const float*)d_in[8];
    const float* Whh  = (const float*)d_in[9];
    const float* bih  = (const float*)d_in[10];
    const float* bhh  = (const float*)d_in[11];
    const float* fc1W = (const float*)d_in[12];
    const float* fc1b = (const float*)d_in[13];
    const float* fc2W = (const float*)d_in[14];
    const float* fc2b = (const float*)d_in[15];
    const float* fc3W = (const float*)d_in[16];
    const float* fc3b = (const float*)d_in[17];
    const float* dh1W = (const float*)d_in[18];
    const float* dh1b = (const float*)d_in[19];
    const float* dh2W = (const float*)d_in[20];
    const float* dh2b = (const float*)d_in[21];

    float* outF = (float*)d_out;
    float* outD = outF + (size_t)Nn * Hh;

    float* tmpW  = symp<float>(g_tmpW);
    float* giAll = symp<float>(g_giAll);
    float* gh    = symp<float>(g_gh);
    float* h1    = symp<float>(g_h1);
    float* h2    = symp<float>(g_h2);
    float* f2    = symp<float>(g_f2);
    float* d1    = symp<float>(g_d1);
    float* cb    = symp<float>(g_cb);
    __nv_bfloat16* xs    = symp<__nv_bfloat16>(g_xs);
    __nv_bfloat16* aggA  = symp<__nv_bfloat16>(g_aggA);
    __nv_bfloat16* seqs  = symp<__nv_bfloat16>(g_seqs);
    __nv_bfloat16* hs    = symp<__nv_bfloat16>(g_hs);
    __nv_bfloat16* f1s   = symp<__nv_bfloat16>(g_f1s);
    __nv_bfloat16* gcnWs = symp<__nv_bfloat16>(g_gcnWs);
    __nv_bfloat16* Wihs  = symp<__nv_bfloat16>(g_Wihs);
    __nv_bfloat16* Whhs  = symp<__nv_bfloat16>(g_Whhs);
    __nv_bfloat16* cWs   = symp<__nv_bfloat16>(g_cWs);
    __nv_bfloat16* fc2Ws = symp<__nv_bfloat16>(g_fc2Ws);

    cudaFuncSetAttribute(gemm_mma<0, 0>, cudaFuncAttributeMaxDynamicSharedMemorySize, GEMM_SMEM);
    cudaFuncSetAttribute(gemm_mma<0, 0>, cudaFuncAttributePreferredSharedMemoryCarveout, 100);
    cudaFuncSetAttribute(gemm_mma<1, 0>, cudaFuncAttributeMaxDynamicSharedMemorySize, GEMM_SMEM);
    cudaFuncSetAttribute(gemm_mma<1, 0>, cudaFuncAttributePreferredSharedMemoryCarveout, 100);
    cudaFuncSetAttribute(gemm_mma<1, 3>, cudaFuncAttributeMaxDynamicSharedMemorySize, GEMM_SMEM);
    cudaFuncSetAttribute(gemm_mma<1, 3>, cudaFuncAttributePreferredSharedMemoryCarveout, 100);

    const int TB = 256;
    const int gN = (Nn + TB - 1) / TB;
    const int gE = (Ee + TB - 1) / TB;

    dim3 blk(256);
    const int RB4 = (SN + 127) / 128;   // 625
    const int RB1 = (Nn + 127) / 128;   // 157
    dim3 gGCN(2, RB4);
    dim3 gGI(6, RB4);
    dim3 gGRU(6, RB1);
    dim3 gHC(2, RB1);
    dim3 gH1(1, RB1);

    // ---- prologue: big GCN GEMM stays at launch slot #4 (ncu -s 5) ----
    k_wsplit_all<<<dim3(64, 9), TB>>>(gcnW, Wih, Whh, fc1W, dh1W, fc2W, fc1b, dh1b);    // #1
    k_split<<<((long)SN * 64 + TB - 1) / TB, TB>>>(x, xs, (long)SN * 64, 64);           // #2
    k_init_deg_cnt<<<gN, TB>>>();                                                       // #3
    gemm_mma<0, 0><<<gGCN, blk, GEMM_SMEM>>>(xs, gcnWs, nullptr, tmpW, nullptr,
                                             SN, 256, 256);                             // #4 <- profile
    // graph preprocessing -> CSR
    k_edge_deg_cnt<<<gE, TB>>>(edst, ew);
    k_scan1<<<NB, 256>>>();
    k_scan2<<<1, 128>>>();
    k_scan3<<<NB, 256>>>();
    k_fill_csr<<<gE, TB>>>(esrc, edst, ew);

    // batched GCN stack
    k_gcn_agg4<<<Nn, 256>>>(tmpW, gcnb + 0 * Dd, lng + 0 * Dd, lnb + 0 * Dd, aggA);
    gemm_mma<0, 0><<<gGCN, blk, GEMM_SMEM>>>(aggA, gcnWs + 1 * 256 * 512, nullptr, tmpW,
                                             nullptr, SN, 256, 256);
    k_gcn_agg4<<<Nn, 256>>>(tmpW, gcnb + 1 * Dd, lng + 1 * Dd, lnb + 1 * Dd, aggA);
    gemm_mma<0, 0><<<gGCN, blk, GEMM_SMEM>>>(aggA, gcnWs + 2 * 256 * 512, nullptr, tmpW,
                                             nullptr, SN, 256, 256);
    k_gcn_agg4<<<Nn, 256>>>(tmpW, gcnb + 2 * Dd, lng + 2 * Dd, lnb + 2 * Dd, seqs);

    // gi for ALL timesteps in one GEMM
    gemm_mma<0, 0><<<gGI, blk, GEMM_SMEM>>>(seqs, Wihs, bih, giAll, nullptr, SN, 768, 256);

    // GRU recurrence
    const int gCell = (Nn * 64 + TB - 1) / TB;
    k_gru_cell<<<gCell, TB>>>(giAll, gh, bhh, h1, h1, hs, 1);
    for (int t = 1; t < Ss; t++) {
        float* hp = (t & 1) ? h1 : h2;
        float* hn = (t & 1) ? h2 : h1;
        gemm_mma<0, 0><<<gGRU, blk, GEMM_SMEM>>>(hs, Whhs, bhh, gh, nullptr, Nn, 768, 256);
        k_gru_cell<<<gCell, TB>>>(giAll + (size_t)t * Nn * 768, gh, bhh, hp, hn, hs, 0);
    }

    // heads
    gemm_mma<1, 3><<<gHC, blk, GEMM_SMEM>>>(hs, cWs, cb, d1, f1s, Nn, 192, 256);
    gemm_mma<1, 0><<<gH1, blk, GEMM_SMEM>>>(f1s, fc2Ws, fc2b, f2, nullptr, Nn, 64, 128);
    k_head5x2<<<dim3((Nn * 32 + TB - 1) / TB, 2), TB>>>(f2, fc3W, fc3b, outF,
                                                        d1, dh2W, dh2b, outD);
}